// round 6
// baseline (speedup 1.0000x reference)
#include <cuda_runtime.h>
#include <cuda_bf16.h>

// Shapes (fixed by the problem)
#define S_      (1 << 20)           // D*H*W = 64*128*128
#define N_      (1 << 21)           // B * S_
#define NW_     (N_ / 32)           // 65536 mask words
#define NROWS_  (N_ / 128)          // 16384 W-rows
#define CAPC    4096
#define TOPN    250

// ---------------- device scratch (static; no allocations) ----------------
__device__ float    g_sim[N_];                      // 8 MB
__device__ unsigned g_pos[NW_], g_t1[NW_], g_t2[NW_];
__device__ unsigned g_dilP[NW_], g_hsm[NW_], g_dilH[NW_];
__device__ int      g_hist[4096];
__device__ int      g_bstar;
__device__ int      g_ccount;
__device__ float    g_cval[CAPC];
__device__ int      g_cidx[CAPC];
__device__ float    g_accA[36];   // [0..31] std sums, [32] ce, [33] sumP1, [34] tp1, [35] cnt(pos)
__device__ float    g_stdn[32];
__device__ float    g_possum, g_msum, g_mcnt, g_fsum, g_fcnt;

__device__ __forceinline__ float warpRed(float x) {
#pragma unroll
    for (int o = 16; o; o >>= 1) x += __shfl_xor_sync(0xffffffffu, x, o);
    return x;
}

// ---------------- 0: zero accumulators + hsm + hist ----------------
__global__ void kInit() {
    int i = blockIdx.x * blockDim.x + threadIdx.x;
    if (i < NW_)  g_hsm[i]  = 0u;
    if (i < 4096) g_hist[i] = 0;
    if (i < 36)   g_accA[i] = 0.f;
    if (i == 0) {
        g_bstar = 0; g_ccount = 0;
        g_possum = 0.f; g_msum = 0.f; g_mcnt = 0.f; g_fsum = 0.f; g_fcnt = 0.f;
    }
}

// ---------------- 1: fused stats pass (feature read #1) ----------------
// Channel-OUTER layout: each thread owns 4 voxel-quads in a contiguous block
// chunk; loops channels with per-channel register accumulators. A warp's
// concurrent loads stay within 1-4 pages (vs 32 in channel-inner layout).
__global__ __launch_bounds__(256) void kA(const float* __restrict__ feat,
                                          const float* __restrict__ net,
                                          const int*   __restrict__ tgt) {
    const int t = threadIdx.x;
    const int lane = t & 31;
    const int qbase = blockIdx.x << 10;       // 1024 quads / block
    const int vbase = qbase << 2;             // 4096 voxels / block (divides S_)
    const int b = vbase >> 20;
    const int sbase = vbase & (S_ - 1);

    float ce = 0.f, sp = 0.f, tp = 0.f, cnt = 0.f;
    unsigned nib[4];
    float m[16];
#pragma unroll
    for (int k = 0; k < 4; k++) {
        const int off = (t + (k << 8)) << 2;  // voxel offset within chunk
        const int v = vbase + off;
        const int s = sbase + off;
        const int4 lb = *reinterpret_cast<const int4*>(tgt + v);
        const float* nb = net + (size_t)b * 2 * S_ + s;
        const float4 x0 = *reinterpret_cast<const float4*>(nb);
        const float4 x1 = *reinterpret_cast<const float4*>(nb + S_);
        float a0[4] = {x0.x, x0.y, x0.z, x0.w};
        float a1[4] = {x1.x, x1.y, x1.z, x1.w};
        int   labs[4] = {lb.x, lb.y, lb.z, lb.w};
        unsigned nn = 0u;
#pragma unroll
        for (int j = 0; j < 4; j++) {
            float mm = fmaxf(a0[j], a1[j]);
            float e0 = __expf(a0[j] - mm), e1 = __expf(a1[j] - mm);
            float sum = e0 + e1;
            float lse = mm + __logf(sum);
            bool pos = (labs[j] == 1);
            ce -= pos ? (a1[j] - lse) : (a0[j] - lse);
            float p1 = e1 / sum;
            sp += p1;
            float pf = pos ? 1.f : 0.f;
            tp += p1 * pf; cnt += pf;
            m[k * 4 + j] = pf;
            nn |= (pos ? 1u : 0u) << j;
        }
        nib[k] = nn;
    }

    // pack pos bits: lanes (8 per word) OR-combine their nibbles
#pragma unroll
    for (int k = 0; k < 4; k++) {
        unsigned part = nib[k] << ((lane & 7) * 4);
        part |= __shfl_xor_sync(0xffffffffu, part, 1);
        part |= __shfl_xor_sync(0xffffffffu, part, 2);
        part |= __shfl_xor_sync(0xffffffffu, part, 4);
        if ((lane & 7) == 0) g_pos[(qbase + t + (k << 8)) >> 3] = part;
    }

    float acc[32];
#pragma unroll
    for (int c = 0; c < 32; c++) acc[c] = 0.f;
    const float* fb = feat + (size_t)b * 32 * S_ + sbase;
#pragma unroll
    for (int c = 0; c < 32; c++) {
        const float* fc = fb + (size_t)c * S_;
        float a = 0.f;
#pragma unroll
        for (int k = 0; k < 4; k++) {
            const float4 f = *reinterpret_cast<const float4*>(fc + ((t + (k << 8)) << 2));
            a += f.x * m[k * 4 + 0] + f.y * m[k * 4 + 1]
               + f.z * m[k * 4 + 2] + f.w * m[k * 4 + 3];
        }
        acc[c] = a;
    }

    // block reduction
#pragma unroll
    for (int c = 0; c < 32; c++) acc[c] = warpRed(acc[c]);
    ce = warpRed(ce); sp = warpRed(sp); tp = warpRed(tp); cnt = warpRed(cnt);

    __shared__ float sh[8][36];
    const int w = threadIdx.x >> 5;
    if (lane == 0) {
#pragma unroll
        for (int c = 0; c < 32; c++) sh[w][c] = acc[c];
        sh[w][32] = ce; sh[w][33] = sp; sh[w][34] = tp; sh[w][35] = cnt;
    }
    __syncthreads();
    if (threadIdx.x < 36) {
        float s = 0.f;
#pragma unroll
        for (int u = 0; u < 8; u++) s += sh[u][threadIdx.x];
        atomicAdd(&g_accA[threadIdx.x], s);
    }
}

// ---------------- 2: normalize std ----------------
__global__ void kA2() {
    int c = threadIdx.x;                // 32 threads
    float cnt = g_accA[35];
    float std = (cnt > 0.f) ? g_accA[c] / fmaxf(cnt, 1.f) : 0.f;
    float sq = std * std;
#pragma unroll
    for (int o = 16; o; o >>= 1) sq += __shfl_xor_sync(0xffffffffu, sq, o);
    float nrm = sqrtf(sq);
    g_stdn[c] = std / fmaxf(nrm, 1e-12f);
}

// ---------------- 3: sim pass (feature read #2) + pos_loss + histogram ----------------
// Channel-outer: each thread owns 2 voxel-quads; d/n accumulators in registers,
// no cross-lane combines at all.
__global__ __launch_bounds__(256) void kB(const float* __restrict__ feat) {
    __shared__ float ssn[32];
    if (threadIdx.x < 32) ssn[threadIdx.x] = g_stdn[threadIdx.x];
    __syncthreads();

    const int t = threadIdx.x;
    const int qbase = blockIdx.x << 9;        // 512 quads / block
    const int vbase = qbase << 2;             // 2048 voxels / block
    const int b = vbase >> 20;
    const int sbase = vbase & (S_ - 1);

    float d[8], n[8];
#pragma unroll
    for (int j = 0; j < 8; j++) { d[j] = 0.f; n[j] = 0.f; }

    const float* fb = feat + (size_t)b * 32 * S_ + sbase;
#pragma unroll
    for (int c = 0; c < 32; c++) {
        const float wc = ssn[c];
        const float* fc = fb + (size_t)c * S_;
#pragma unroll
        for (int k = 0; k < 2; k++) {
            const float4 f = *reinterpret_cast<const float4*>(fc + ((t + (k << 8)) << 2));
            d[k * 4 + 0] += f.x * wc; n[k * 4 + 0] += f.x * f.x;
            d[k * 4 + 1] += f.y * wc; n[k * 4 + 1] += f.y * f.y;
            d[k * 4 + 2] += f.z * wc; n[k * 4 + 2] += f.z * f.z;
            d[k * 4 + 3] += f.w * wc; n[k * 4 + 3] += f.w * f.w;
        }
    }

    float psum = 0.f;
#pragma unroll
    for (int k = 0; k < 2; k++) {
        const int q = qbase + t + (k << 8);
        const int v = q << 2;
        float sims[4];
#pragma unroll
        for (int j = 0; j < 4; j++)
            sims[j] = d[k * 4 + j] / fmaxf(sqrtf(n[k * 4 + j]), 1e-12f);
        *reinterpret_cast<float4*>(g_sim + v) = make_float4(sims[0], sims[1], sims[2], sims[3]);

        const unsigned pw = g_pos[q >> 3];
        const unsigned base = (q & 7) * 4;
#pragma unroll
        for (int j = 0; j < 4; j++) {
            bool pos = (pw >> (base + j)) & 1u;
            if (pos) {
                psum += 1.f - sims[j];
            } else {
                int bin = (int)((sims[j] + 1.0f) * 2048.0f);
                bin = max(0, min(4095, bin));
                atomicAdd(&g_hist[bin], 1);
            }
        }
    }

    psum = warpRed(psum);
    __shared__ float shp[8];
    if ((threadIdx.x & 31) == 0) shp[threadIdx.x >> 5] = psum;
    __syncthreads();
    if (threadIdx.x == 0) {
        float s = 0.f;
#pragma unroll
        for (int u = 0; u < 8; u++) s += shp[u];
        atomicAdd(&g_possum, s);
    }
}

// ---------------- bit-packed separable Chebyshev-10 dilation ----------------
__global__ void kDilW(int which) {      // in (pos|hsm) -> g_t1
    const unsigned* in = which ? g_hsm : g_pos;
    int r = blockIdx.x * blockDim.x + threadIdx.x;
    if (r >= NROWS_) return;
    unsigned a0 = in[r * 4 + 0], a1 = in[r * 4 + 1], a2 = in[r * 4 + 2], a3 = in[r * 4 + 3];
    unsigned c0 = a0, c1 = a1, c2 = a2, c3 = a3;
#pragma unroll
    for (int s = 1; s <= 10; s++) {
        c0 |= (a0 << s) | __funnelshift_r(a0, a1, s);
        c1 |= __funnelshift_l(a0, a1, s) | __funnelshift_r(a1, a2, s);
        c2 |= __funnelshift_l(a1, a2, s) | __funnelshift_r(a2, a3, s);
        c3 |= __funnelshift_l(a2, a3, s) | (a3 >> s);
    }
    g_t1[r * 4 + 0] = c0; g_t1[r * 4 + 1] = c1; g_t1[r * 4 + 2] = c2; g_t1[r * 4 + 3] = c3;
}

__global__ void kDilH() {               // g_t1 -> g_t2
    int w = blockIdx.x * blockDim.x + threadIdx.x;
    if (w >= NW_) return;
    int k = w & 3, h = (w >> 2) & 127, base = (w >> 9) << 9;
    int h0 = max(h - 10, 0), h1 = min(h + 10, 127);
    unsigned acc = 0u;
    for (int hh = h0; hh <= h1; hh++) acc |= g_t1[base + (hh << 2) + k];
    g_t2[w] = acc;
}

__global__ void kDilD(int which) {      // g_t2 -> (dilP|dilH)
    int w = blockIdx.x * blockDim.x + threadIdx.x;
    if (w >= NW_) return;
    int j = w & 511, d = (w >> 9) & 63, base = (w >> 15) << 15;
    int d0 = max(d - 10, 0), d1 = min(d + 10, 63);
    unsigned acc = 0u;
    for (int dd = d0; dd <= d1; dd++) acc |= g_t2[base + (dd << 9) + j];
    (which ? g_dilH : g_dilP)[w] = acc;
}

// ---------------- top-k threshold bin via suffix scan ----------------
__global__ void kT1() {
    __shared__ int shh[4096];
    __shared__ int ssum[1024];
    int t = threadIdx.x;
#pragma unroll
    for (int k = 0; k < 4; k++) shh[t * 4 + k] = g_hist[t * 4 + k];
    __syncthreads();
    ssum[t] = shh[t * 4] + shh[t * 4 + 1] + shh[t * 4 + 2] + shh[t * 4 + 3];
    __syncthreads();
    for (int off = 1; off < 1024; off <<= 1) {
        int add = (t + off < 1024) ? ssum[t + off] : 0;
        __syncthreads();
        ssum[t] += add;
        __syncthreads();
    }
    int run = (t < 1023) ? ssum[t + 1] : 0;   // suffix count strictly below this chunk's bins
    for (int k = 3; k >= 0; k--) {
        int nr = run + shh[t * 4 + k];
        if (run < TOPN && nr >= TOPN) g_bstar = t * 4 + k;  // exactly one thread writes
        run = nr;
    }
}

// ---------------- gather candidates >= threshold bin ----------------
__global__ void kG() {
    const int stride = gridDim.x * blockDim.x;
    const int bstar = g_bstar;
    for (int i = blockIdx.x * blockDim.x + threadIdx.x; i < N_ / 4; i += stride) {
        const int v = i << 2;
        const unsigned pw = g_pos[v >> 5];
        const float4 sm = *reinterpret_cast<const float4*>(g_sim + v);
        float sims[4] = {sm.x, sm.y, sm.z, sm.w};
        const unsigned base = v & 31;
#pragma unroll
        for (int j = 0; j < 4; j++) {
            bool pos = (pw >> (base + j)) & 1u;
            if (!pos) {
                int bin = (int)((sims[j] + 1.0f) * 2048.0f);
                bin = max(0, min(4095, bin));
                if (bin >= bstar) {
                    int id = atomicAdd(&g_ccount, 1);
                    if (id < CAPC) { g_cval[id] = sims[j]; g_cidx[id] = v + j; }
                }
            }
        }
    }
}

// ---------------- exact top-250 selection (top_k tie-break: value desc, index asc) ----------------
__global__ void kS() {
    __shared__ float sv[CAPC];
    __shared__ int   si[CAPC];
    int K = g_ccount; if (K > CAPC) K = CAPC;
    for (int i = threadIdx.x; i < K; i += blockDim.x) { sv[i] = g_cval[i]; si[i] = g_cidx[i]; }
    __syncthreads();
    for (int i = threadIdx.x; i < K; i += blockDim.x) {
        float v = sv[i]; int id = si[i];
        int rank = 0;
        for (int j = 0; j < K; j++) {
            float vj = sv[j];
            rank += (vj > v) || (vj == v && si[j] < id);
        }
        if (rank < TOPN) atomicOr(&g_hsm[id >> 5], 1u << (id & 31));
    }
}

// ---------------- mis + fin accumulation ----------------
__global__ __launch_bounds__(256) void kF() {
    float ms = 0.f, mc = 0.f, fs = 0.f, fc = 0.f;
    const int stride = gridDim.x * blockDim.x;
    for (int i = blockIdx.x * blockDim.x + threadIdx.x; i < N_ / 4; i += stride) {
        const int v = i << 2;
        const unsigned pw = g_pos[v >> 5], dp = g_dilP[v >> 5], dh = g_dilH[v >> 5];
        const float4 sm = *reinterpret_cast<const float4*>(g_sim + v);
        float sims[4] = {sm.x, sm.y, sm.z, sm.w};
        const unsigned base = v & 31;
#pragma unroll
        for (int j = 0; j < 4; j++) {
            unsigned bit = base + j;
            bool pos = (pw >> bit) & 1u;
            float r = fmaxf(sims[j], 0.f);
            if (((dp >> bit) & 1u) && !pos) { ms += r; mc += 1.f; }
            if (((dh >> bit) & 1u) && !pos) { fs += r; fc += 1.f; }
        }
    }
    ms = warpRed(ms); mc = warpRed(mc); fs = warpRed(fs); fc = warpRed(fc);
    __shared__ float sh4[8][4];
    if ((threadIdx.x & 31) == 0) {
        int w = threadIdx.x >> 5;
        sh4[w][0] = ms; sh4[w][1] = mc; sh4[w][2] = fs; sh4[w][3] = fc;
    }
    __syncthreads();
    if (threadIdx.x < 4) {
        float t = 0.f;
#pragma unroll
        for (int u = 0; u < 8; u++) t += sh4[u][threadIdx.x];
        if      (threadIdx.x == 0) atomicAdd(&g_msum, t);
        else if (threadIdx.x == 1) atomicAdd(&g_mcnt, t);
        else if (threadIdx.x == 2) atomicAdd(&g_fsum, t);
        else                       atomicAdd(&g_fcnt, t);
    }
}

// ---------------- final combine ----------------
__global__ void kZ(float* __restrict__ out) {
    const float Nf = (float)N_;
    float ce  = g_accA[32] / Nf;
    float sp  = g_accA[33], tp = g_accA[34], cnt = g_accA[35];
    float dc  = (2.f * tp + 1e-5f) / (sp + cnt + 1e-5f + 1e-8f);
    float dice = -dc;
    float pl = (cnt    > 0.f) ? g_possum / fmaxf(cnt,    1.f) : 0.f;
    float ml = (g_mcnt > 0.f) ? g_msum   / fmaxf(g_mcnt, 1.f) : 0.f;
    float nl = (g_fcnt > 0.f) ? g_fsum   / fmaxf(g_fcnt, 1.f) : 0.f;
    out[0] = ce + dice + 5.f * (pl + ml + nl);
}

// ---------------- launch ----------------
extern "C" void kernel_launch(void* const* d_in, const int* in_sizes, int n_in,
                              void* d_out, int out_size) {
    const float* feat = (const float*)d_in[0];
    const float* net  = (const float*)d_in[1];
    const int*   tgt  = (const int*)d_in[2];
    float* out = (float*)d_out;

    kInit<<<256, 256>>>();
    kA<<<512, 256>>>(feat, net, tgt);     // 1024 quads (4096 voxels) per block
    kA2<<<1, 32>>>();
    kB<<<1024, 256>>>(feat);              // 512 quads (2048 voxels) per block

    // dilate pos mask
    kDilW<<<64, 256>>>(0);
    kDilH<<<256, 256>>>();
    kDilD<<<256, 256>>>(0);

    // exact top-250 of neg sims
    kT1<<<1, 1024>>>();
    kG<<<256, 256>>>();
    kS<<<1, 256>>>();

    // dilate hsm mask
    kDilW<<<64, 256>>>(1);
    kDilH<<<256, 256>>>();
    kDilD<<<256, 256>>>(1);

    kF<<<512, 256>>>();
    kZ<<<1, 1>>>(out);
}

// round 8
// speedup vs baseline: 1.0395x; 1.0395x over previous
#include <cuda_runtime.h>
#include <cuda_bf16.h>
#include <cstdint>

// Shapes (fixed by the problem)
#define S_      (1 << 20)           // D*H*W = 64*128*128
#define N_      (1 << 21)           // B * S_
#define NW_     (N_ / 32)           // 65536 mask words
#define NROWS_  (N_ / 128)          // 16384 W-rows
#define CAPC    4096
#define TOPN    250

#define DST       5                 // pipeline depth (stages)
#define CHUNK_V   2048              // voxels per block
#define CH_BYTES  (CHUNK_V * 4)     // 8192 bytes per channel tile

// ---------------- device scratch (static; no allocations) ----------------
__device__ float    g_sim[N_];                      // 8 MB
__device__ unsigned g_pos[NW_], g_t1[NW_], g_t2[NW_];
__device__ unsigned g_dilP[NW_], g_hsm[NW_], g_dilH[NW_];
__device__ int      g_hist[4096];
__device__ int      g_bstar;
__device__ int      g_ccount;
__device__ float    g_cval[CAPC];
__device__ int      g_cidx[CAPC];
__device__ float    g_accA[36];   // [0..31] std sums, [32] ce, [33] sumP1, [34] tp1, [35] cnt(pos)
__device__ float    g_stdn[32];
__device__ float    g_possum, g_msum, g_mcnt, g_fsum, g_fcnt;

__device__ __forceinline__ float warpRed(float x) {
#pragma unroll
    for (int o = 16; o; o >>= 1) x += __shfl_xor_sync(0xffffffffu, x, o);
    return x;
}

__device__ __forceinline__ uint32_t smem_u32(const void* p) {
    uint32_t a;
    asm("{ .reg .u64 t; cvta.to.shared.u64 t, %1; cvt.u32.u64 %0, t; }" : "=r"(a) : "l"(p));
    return a;
}
__device__ __forceinline__ void mbar_init(uint32_t mb, uint32_t cnt) {
    asm volatile("mbarrier.init.shared.b64 [%0], %1;" :: "r"(mb), "r"(cnt) : "memory");
}
__device__ __forceinline__ void mbar_expect_tx(uint32_t mb, uint32_t bytes) {
    asm volatile("mbarrier.arrive.expect_tx.shared.b64 _, [%0], %1;" :: "r"(mb), "r"(bytes) : "memory");
}
__device__ __forceinline__ void mbar_wait(uint32_t mb, uint32_t parity) {
    asm volatile(
        "{\n\t.reg .pred P;\n\t"
        "W_%=:\n\t"
        "mbarrier.try_wait.parity.acquire.cta.shared::cta.b64 P, [%0], %1, 0x989680;\n\t"
        "@P bra D_%=;\n\t"
        "bra W_%=;\n\t"
        "D_%=:\n\t}"
        :: "r"(mb), "r"(parity) : "memory");
}
__device__ __forceinline__ void bulk_g2s(uint32_t dst, const void* src, uint32_t bytes, uint32_t mb) {
    asm volatile(
        "cp.async.bulk.shared::cta.global.mbarrier::complete_tx::bytes [%0], [%1], %2, [%3];"
        :: "r"(dst), "l"(src), "r"(bytes), "r"(mb) : "memory");
}

// ---------------- 0: zero accumulators + hsm + hist ----------------
__global__ void kInit() {
    int i = blockIdx.x * blockDim.x + threadIdx.x;
    if (i < NW_)  g_hsm[i]  = 0u;
    if (i < 4096) g_hist[i] = 0;
    if (i < 36)   g_accA[i] = 0.f;
    if (i == 0) {
        g_bstar = 0; g_ccount = 0;
        g_possum = 0.f; g_msum = 0.f; g_mcnt = 0.f; g_fsum = 0.f; g_fcnt = 0.f;
    }
}

// ---------------- 1: fused stats pass (feature read #1, bulk-async staged) ----------------
// Block owns 2048 contiguous voxels. Feature channels streamed through a 5-deep
// SMEM ring via cp.async.bulk. Refill safety = __syncthreads() after each
// channel's compute (no empty-barriers; hang-proof).
__global__ __launch_bounds__(256) void kA(const float* __restrict__ feat,
                                          const float* __restrict__ net,
                                          const int*   __restrict__ tgt) {
    __shared__ __align__(128) float sbuf[DST][CHUNK_V];
    __shared__ uint64_t mbF[DST];
    __shared__ float swacc[8][32];
    __shared__ float shs[8][4];

    const int t = threadIdx.x;
    const int lane = t & 31;
    const int w = t >> 5;
    const int vbase = blockIdx.x << 11;          // 2048 voxels per block
    const int b = vbase >> 20;
    const int sbase = vbase & (S_ - 1);
    const float* fsrc = feat + (size_t)b * 32 * S_ + sbase;

    uint32_t fbar[DST], baddr[DST];
#pragma unroll
    for (int s = 0; s < DST; s++) {
        fbar[s] = smem_u32(&mbF[s]);
        baddr[s] = smem_u32(&sbuf[s][0]);
    }

    if (t == 0) {
#pragma unroll
        for (int s = 0; s < DST; s++) mbar_init(fbar[s], 1);
    }
    swacc[w][lane] = 0.f;          // each warp zeroes its own accumulator row
    __syncthreads();

    if (t == 0) {
#pragma unroll
        for (int s = 0; s < DST; s++) {
            mbar_expect_tx(fbar[s], CH_BYTES);
            bulk_g2s(baddr[s], fsrc + (size_t)s * S_, CH_BYTES, fbar[s]);
        }
    }

    // ---- CE / softmax / masks / pos-bit packing (overlaps with async fills) ----
    float ce = 0.f, sp = 0.f, tp = 0.f, cnt = 0.f;
    float m[8];
    const int qbase = vbase >> 2;
#pragma unroll
    for (int k = 0; k < 2; k++) {
        const int off = (t + (k << 8)) << 2;
        const int v = vbase + off;
        const int s = sbase + off;
        const int4 lb = *reinterpret_cast<const int4*>(tgt + v);
        const float* nb = net + (size_t)b * 2 * S_ + s;
        const float4 x0 = *reinterpret_cast<const float4*>(nb);
        const float4 x1 = *reinterpret_cast<const float4*>(nb + S_);
        float a0[4] = {x0.x, x0.y, x0.z, x0.w};
        float a1[4] = {x1.x, x1.y, x1.z, x1.w};
        int   labs[4] = {lb.x, lb.y, lb.z, lb.w};
        unsigned nn = 0u;
#pragma unroll
        for (int j = 0; j < 4; j++) {
            float mm = fmaxf(a0[j], a1[j]);
            float e0 = __expf(a0[j] - mm), e1 = __expf(a1[j] - mm);
            float sum = e0 + e1;
            float lse = mm + __logf(sum);
            bool pos = (labs[j] == 1);
            ce -= pos ? (a1[j] - lse) : (a0[j] - lse);
            float p1 = e1 / sum;
            sp += p1;
            float pf = pos ? 1.f : 0.f;
            tp += p1 * pf; cnt += pf;
            m[k * 4 + j] = pf;
            nn |= (pos ? 1u : 0u) << j;
        }
        unsigned part = nn << ((lane & 7) * 4);
        part |= __shfl_xor_sync(0xffffffffu, part, 1);
        part |= __shfl_xor_sync(0xffffffffu, part, 2);
        part |= __shfl_xor_sync(0xffffffffu, part, 4);
        if ((lane & 7) == 0) g_pos[(qbase + t + (k << 8)) >> 3] = part;
    }

    // ---- channel pipeline: masked sums per channel ----
    for (int c = 0; c < 32; c++) {
        const int s = c % DST;
        const int par = (c / DST) & 1;
        mbar_wait(fbar[s], par);
        const float4 f0 = *reinterpret_cast<const float4*>(&sbuf[s][t << 2]);
        const float4 f1 = *reinterpret_cast<const float4*>(&sbuf[s][(t << 2) + 1024]);
        float p = f0.x * m[0] + f0.y * m[1] + f0.z * m[2] + f0.w * m[3]
                + f1.x * m[4] + f1.y * m[5] + f1.z * m[6] + f1.w * m[7];
        p = warpRed(p);
        if (lane == 0) swacc[w][c] += p;
        __syncthreads();              // everyone done reading sbuf[s]
        const int cn = c + DST;
        if (t == 0 && cn < 32) {
            mbar_expect_tx(fbar[s], CH_BYTES);
            bulk_g2s(baddr[s], fsrc + (size_t)cn * S_, CH_BYTES, fbar[s]);
        }
    }

    // ---- block reductions ----
    ce = warpRed(ce); sp = warpRed(sp); tp = warpRed(tp); cnt = warpRed(cnt);
    if (lane == 0) { shs[w][0] = ce; shs[w][1] = sp; shs[w][2] = tp; shs[w][3] = cnt; }
    __syncthreads();
    if (t < 32) {
        float a = 0.f;
#pragma unroll
        for (int u = 0; u < 8; u++) a += swacc[u][t];
        atomicAdd(&g_accA[t], a);
    }
    if (t < 4) {
        float a = 0.f;
#pragma unroll
        for (int u = 0; u < 8; u++) a += shs[u][t];
        atomicAdd(&g_accA[32 + t], a);
    }
}

// ---------------- 2: normalize std ----------------
__global__ void kA2() {
    int c = threadIdx.x;                // 32 threads
    float cnt = g_accA[35];
    float std = (cnt > 0.f) ? g_accA[c] / fmaxf(cnt, 1.f) : 0.f;
    float sq = std * std;
#pragma unroll
    for (int o = 16; o; o >>= 1) sq += __shfl_xor_sync(0xffffffffu, sq, o);
    float nrm = sqrtf(sq);
    g_stdn[c] = std / fmaxf(nrm, 1e-12f);
}

// ---------------- 3: sim pass (feature read #2, bulk-async staged) + pos_loss + hist ----------------
__global__ __launch_bounds__(256) void kB(const float* __restrict__ feat) {
    __shared__ __align__(128) float sbuf[DST][CHUNK_V];
    __shared__ uint64_t mbF[DST];
    __shared__ float ssn[32];
    __shared__ float shp[8];

    const int t = threadIdx.x;
    const int lane = t & 31;
    const int vbase = blockIdx.x << 11;
    const int b = vbase >> 20;
    const int sbase = vbase & (S_ - 1);
    const float* fsrc = feat + (size_t)b * 32 * S_ + sbase;

    uint32_t fbar[DST], baddr[DST];
#pragma unroll
    for (int s = 0; s < DST; s++) {
        fbar[s] = smem_u32(&mbF[s]);
        baddr[s] = smem_u32(&sbuf[s][0]);
    }
    if (t < 32) ssn[t] = g_stdn[t];
    if (t == 0) {
#pragma unroll
        for (int s = 0; s < DST; s++) mbar_init(fbar[s], 1);
    }
    __syncthreads();
    if (t == 0) {
#pragma unroll
        for (int s = 0; s < DST; s++) {
            mbar_expect_tx(fbar[s], CH_BYTES);
            bulk_g2s(baddr[s], fsrc + (size_t)s * S_, CH_BYTES, fbar[s]);
        }
    }

    float d[8], n[8];
#pragma unroll
    for (int j = 0; j < 8; j++) { d[j] = 0.f; n[j] = 0.f; }

    for (int c = 0; c < 32; c++) {
        const int s = c % DST;
        const int par = (c / DST) & 1;
        mbar_wait(fbar[s], par);
        const float4 f0 = *reinterpret_cast<const float4*>(&sbuf[s][t << 2]);
        const float4 f1 = *reinterpret_cast<const float4*>(&sbuf[s][(t << 2) + 1024]);
        const float wc = ssn[c];
        d[0] += f0.x * wc; n[0] += f0.x * f0.x;
        d[1] += f0.y * wc; n[1] += f0.y * f0.y;
        d[2] += f0.z * wc; n[2] += f0.z * f0.z;
        d[3] += f0.w * wc; n[3] += f0.w * f0.w;
        d[4] += f1.x * wc; n[4] += f1.x * f1.x;
        d[5] += f1.y * wc; n[5] += f1.y * f1.y;
        d[6] += f1.z * wc; n[6] += f1.z * f1.z;
        d[7] += f1.w * wc; n[7] += f1.w * f1.w;
        __syncthreads();              // everyone done reading sbuf[s]
        const int cn = c + DST;
        if (t == 0 && cn < 32) {
            mbar_expect_tx(fbar[s], CH_BYTES);
            bulk_g2s(baddr[s], fsrc + (size_t)cn * S_, CH_BYTES, fbar[s]);
        }
    }

    // ---- epilogue: sims, pos_loss, histogram ----
    float psum = 0.f;
    const int qbase = vbase >> 2;
#pragma unroll
    for (int k = 0; k < 2; k++) {
        const int q = qbase + t + (k << 8);
        const int v = q << 2;
        float sims[4];
#pragma unroll
        for (int j = 0; j < 4; j++)
            sims[j] = d[k * 4 + j] / fmaxf(sqrtf(n[k * 4 + j]), 1e-12f);
        *reinterpret_cast<float4*>(g_sim + v) = make_float4(sims[0], sims[1], sims[2], sims[3]);

        const unsigned pw = g_pos[q >> 3];
        const unsigned base = (q & 7) * 4;
#pragma unroll
        for (int j = 0; j < 4; j++) {
            bool pos = (pw >> (base + j)) & 1u;
            if (pos) {
                psum += 1.f - sims[j];
            } else {
                int bin = (int)((sims[j] + 1.0f) * 2048.0f);
                bin = max(0, min(4095, bin));
                atomicAdd(&g_hist[bin], 1);
            }
        }
    }

    psum = warpRed(psum);
    if (lane == 0) shp[t >> 5] = psum;
    __syncthreads();
    if (t == 0) {
        float a = 0.f;
#pragma unroll
        for (int u = 0; u < 8; u++) a += shp[u];
        atomicAdd(&g_possum, a);
    }
}

// ---------------- bit-packed separable Chebyshev-10 dilation ----------------
__global__ void kDilW(int which) {      // in (pos|hsm) -> g_t1
    const unsigned* in = which ? g_hsm : g_pos;
    int r = blockIdx.x * blockDim.x + threadIdx.x;
    if (r >= NROWS_) return;
    unsigned a0 = in[r * 4 + 0], a1 = in[r * 4 + 1], a2 = in[r * 4 + 2], a3 = in[r * 4 + 3];
    unsigned c0 = a0, c1 = a1, c2 = a2, c3 = a3;
#pragma unroll
    for (int s = 1; s <= 10; s++) {
        c0 |= (a0 << s) | __funnelshift_r(a0, a1, s);
        c1 |= __funnelshift_l(a0, a1, s) | __funnelshift_r(a1, a2, s);
        c2 |= __funnelshift_l(a1, a2, s) | __funnelshift_r(a2, a3, s);
        c3 |= __funnelshift_l(a2, a3, s) | (a3 >> s);
    }
    g_t1[r * 4 + 0] = c0; g_t1[r * 4 + 1] = c1; g_t1[r * 4 + 2] = c2; g_t1[r * 4 + 3] = c3;
}

__global__ void kDilH() {               // g_t1 -> g_t2
    int w = blockIdx.x * blockDim.x + threadIdx.x;
    if (w >= NW_) return;
    int k = w & 3, h = (w >> 2) & 127, base = (w >> 9) << 9;
    int h0 = max(h - 10, 0), h1 = min(h + 10, 127);
    unsigned acc = 0u;
    for (int hh = h0; hh <= h1; hh++) acc |= g_t1[base + (hh << 2) + k];
    g_t2[w] = acc;
}

__global__ void kDilD(int which) {      // g_t2 -> (dilP|dilH)
    int w = blockIdx.x * blockDim.x + threadIdx.x;
    if (w >= NW_) return;
    int j = w & 511, d = (w >> 9) & 63, base = (w >> 15) << 15;
    int d0 = max(d - 10, 0), d1 = min(d + 10, 63);
    unsigned acc = 0u;
    for (int dd = d0; dd <= d1; dd++) acc |= g_t2[base + (dd << 9) + j];
    (which ? g_dilH : g_dilP)[w] = acc;
}

// ---------------- top-k threshold bin via suffix scan ----------------
__global__ void kT1() {
    __shared__ int shh[4096];
    __shared__ int ssum[1024];
    int t = threadIdx.x;
#pragma unroll
    for (int k = 0; k < 4; k++) shh[t * 4 + k] = g_hist[t * 4 + k];
    __syncthreads();
    ssum[t] = shh[t * 4] + shh[t * 4 + 1] + shh[t * 4 + 2] + shh[t * 4 + 3];
    __syncthreads();
    for (int off = 1; off < 1024; off <<= 1) {
        int add = (t + off < 1024) ? ssum[t + off] : 0;
        __syncthreads();
        ssum[t] += add;
        __syncthreads();
    }
    int run = (t < 1023) ? ssum[t + 1] : 0;   // suffix count strictly below this chunk's bins
    for (int k = 3; k >= 0; k--) {
        int nr = run + shh[t * 4 + k];
        if (run < TOPN && nr >= TOPN) g_bstar = t * 4 + k;  // exactly one thread writes
        run = nr;
    }
}

// ---------------- gather candidates >= threshold bin ----------------
__global__ void kG() {
    const int stride = gridDim.x * blockDim.x;
    const int bstar = g_bstar;
    for (int i = blockIdx.x * blockDim.x + threadIdx.x; i < N_ / 4; i += stride) {
        const int v = i << 2;
        const unsigned pw = g_pos[v >> 5];
        const float4 sm = *reinterpret_cast<const float4*>(g_sim + v);
        float sims[4] = {sm.x, sm.y, sm.z, sm.w};
        const unsigned base = v & 31;
#pragma unroll
        for (int j = 0; j < 4; j++) {
            bool pos = (pw >> (base + j)) & 1u;
            if (!pos) {
                int bin = (int)((sims[j] + 1.0f) * 2048.0f);
                bin = max(0, min(4095, bin));
                if (bin >= bstar) {
                    int id = atomicAdd(&g_ccount, 1);
                    if (id < CAPC) { g_cval[id] = sims[j]; g_cidx[id] = v + j; }
                }
            }
        }
    }
}

// ---------------- exact top-250 selection (top_k tie-break: value desc, index asc) ----------------
__global__ void kS() {
    __shared__ float sv[CAPC];
    __shared__ int   si[CAPC];
    int K = g_ccount; if (K > CAPC) K = CAPC;
    for (int i = threadIdx.x; i < K; i += blockDim.x) { sv[i] = g_cval[i]; si[i] = g_cidx[i]; }
    __syncthreads();
    for (int i = threadIdx.x; i < K; i += blockDim.x) {
        float v = sv[i]; int id = si[i];
        int rank = 0;
        for (int j = 0; j < K; j++) {
            float vj = sv[j];
            rank += (vj > v) || (vj == v && si[j] < id);
        }
        if (rank < TOPN) atomicOr(&g_hsm[id >> 5], 1u << (id & 31));
    }
}

// ---------------- mis + fin accumulation ----------------
__global__ __launch_bounds__(256) void kF() {
    float ms = 0.f, mc = 0.f, fs = 0.f, fc = 0.f;
    const int stride = gridDim.x * blockDim.x;
    for (int i = blockIdx.x * blockDim.x + threadIdx.x; i < N_ / 4; i += stride) {
        const int v = i << 2;
        const unsigned pw = g_pos[v >> 5], dp = g_dilP[v >> 5], dh = g_dilH[v >> 5];
        const float4 sm = *reinterpret_cast<const float4*>(g_sim + v);
        float sims[4] = {sm.x, sm.y, sm.z, sm.w};
        const unsigned base = v & 31;
#pragma unroll
        for (int j = 0; j < 4; j++) {
            unsigned bit = base + j;
            bool pos = (pw >> bit) & 1u;
            float r = fmaxf(sims[j], 0.f);
            if (((dp >> bit) & 1u) && !pos) { ms += r; mc += 1.f; }
            if (((dh >> bit) & 1u) && !pos) { fs += r; fc += 1.f; }
        }
    }
    ms = warpRed(ms); mc = warpRed(mc); fs = warpRed(fs); fc = warpRed(fc);
    __shared__ float sh4[8][4];
    if ((threadIdx.x & 31) == 0) {
        int w = threadIdx.x >> 5;
        sh4[w][0] = ms; sh4[w][1] = mc; sh4[w][2] = fs; sh4[w][3] = fc;
    }
    __syncthreads();
    if (threadIdx.x < 4) {
        float t = 0.f;
#pragma unroll
        for (int u = 0; u < 8; u++) t += sh4[u][threadIdx.x];
        if      (threadIdx.x == 0) atomicAdd(&g_msum, t);
        else if (threadIdx.x == 1) atomicAdd(&g_mcnt, t);
        else if (threadIdx.x == 2) atomicAdd(&g_fsum, t);
        else                       atomicAdd(&g_fcnt, t);
    }
}

// ---------------- final combine ----------------
__global__ void kZ(float* __restrict__ out) {
    const float Nf = (float)N_;
    float ce  = g_accA[32] / Nf;
    float sp  = g_accA[33], tp = g_accA[34], cnt = g_accA[35];
    float dc  = (2.f * tp + 1e-5f) / (sp + cnt + 1e-5f + 1e-8f);
    float dice = -dc;
    float pl = (cnt    > 0.f) ? g_possum / fmaxf(cnt,    1.f) : 0.f;
    float ml = (g_mcnt > 0.f) ? g_msum   / fmaxf(g_mcnt, 1.f) : 0.f;
    float nl = (g_fcnt > 0.f) ? g_fsum   / fmaxf(g_fcnt, 1.f) : 0.f;
    out[0] = ce + dice + 5.f * (pl + ml + nl);
}

// ---------------- launch ----------------
extern "C" void kernel_launch(void* const* d_in, const int* in_sizes, int n_in,
                              void* d_out, int out_size) {
    const float* feat = (const float*)d_in[0];
    const float* net  = (const float*)d_in[1];
    const int*   tgt  = (const int*)d_in[2];
    float* out = (float*)d_out;

    kInit<<<256, 256>>>();
    kA<<<N_ / CHUNK_V, 256>>>(feat, net, tgt);   // 1024 blocks
    kA2<<<1, 32>>>();
    kB<<<N_ / CHUNK_V, 256>>>(feat);             // 1024 blocks

    // dilate pos mask
    kDilW<<<64, 256>>>(0);
    kDilH<<<256, 256>>>();
    kDilD<<<256, 256>>>(0);

    // exact top-250 of neg sims
    kT1<<<1, 1024>>>();
    kG<<<256, 256>>>();
    kS<<<1, 256>>>();

    // dilate hsm mask
    kDilW<<<64, 256>>>(1);
    kDilH<<<256, 256>>>();
    kDilD<<<256, 256>>>(1);

    kF<<<512, 256>>>();
    kZ<<<1, 1>>>(out);
}

// round 9
// speedup vs baseline: 1.1526x; 1.1088x over previous
#include <cuda_runtime.h>
#include <cuda_bf16.h>

// Shapes (fixed by the problem)
#define S_      (1 << 20)           // D*H*W = 64*128*128
#define N_      (1 << 21)           // B * S_
#define NW_     (N_ / 32)           // 65536 mask words
#define NROWS_  (N_ / 128)          // 16384 W-rows
#define CAPC    4096
#define TOPN    250

// ---------------- device scratch (static; no allocations) ----------------
__device__ float    g_sim[N_];                      // 8 MB
__device__ unsigned g_pos[NW_], g_t1[NW_], g_t2[NW_];
__device__ unsigned g_dilP[NW_], g_hsm[NW_], g_dilH[NW_];
__device__ int      g_hist[4096];
__device__ int      g_bstar;
__device__ int      g_ccount;
__device__ float    g_cval[CAPC];
__device__ int      g_cidx[CAPC];
__device__ float    g_accA[36];   // [0..31] std sums, [32] ce, [33] sumP1, [34] tp1, [35] cnt(pos)
__device__ float    g_stdn[32];
__device__ float    g_possum, g_msum, g_mcnt, g_fsum, g_fcnt;

__device__ __forceinline__ float warpRed(float x) {
#pragma unroll
    for (int o = 16; o; o >>= 1) x += __shfl_xor_sync(0xffffffffu, x, o);
    return x;
}

// ---------------- 0: zero accumulators + hsm + hist ----------------
__global__ void kInit() {
    int i = blockIdx.x * blockDim.x + threadIdx.x;
    if (i < NW_)  g_hsm[i]  = 0u;
    if (i < 4096) g_hist[i] = 0;
    if (i < 36)   g_accA[i] = 0.f;
    if (i == 0) {
        g_bstar = 0; g_ccount = 0;
        g_possum = 0.f; g_msum = 0.f; g_mcnt = 0.f; g_fsum = 0.f; g_fcnt = 0.f;
    }
}

// ---------------- 1: fused stats pass (feature read #1, FORWARD order) ----------------
// CE sum, sum(p1), tp1, pos count, per-channel masked feature sums, pos bitmask.
__global__ __launch_bounds__(256) void kA(const float* __restrict__ feat,
                                          const float* __restrict__ net,
                                          const int*   __restrict__ tgt) {
    float acc[32];
#pragma unroll
    for (int c = 0; c < 32; c++) acc[c] = 0.f;
    float ce = 0.f, sp = 0.f, tp = 0.f, cnt = 0.f;
    const int lane = threadIdx.x & 31;
    const int stride = gridDim.x * blockDim.x;

    for (int i = blockIdx.x * blockDim.x + threadIdx.x; i < N_ / 4; i += stride) {
        const int v = i << 2;
        const int b = v >> 20;
        const int s = v & (S_ - 1);

        const int4 lb = *reinterpret_cast<const int4*>(tgt + v);
        const float* nb = net + (size_t)b * 2 * S_ + s;
        const float4 x0 = *reinterpret_cast<const float4*>(nb);
        const float4 x1 = *reinterpret_cast<const float4*>(nb + S_);

        float a0[4] = {x0.x, x0.y, x0.z, x0.w};
        float a1[4] = {x1.x, x1.y, x1.z, x1.w};
        int   labs[4] = {lb.x, lb.y, lb.z, lb.w};
        float msk[4];
        unsigned nib = 0u;
#pragma unroll
        for (int j = 0; j < 4; j++) {
            float m  = fmaxf(a0[j], a1[j]);
            float e0 = __expf(a0[j] - m), e1 = __expf(a1[j] - m);
            float sum = e0 + e1;
            float lse = m + __logf(sum);
            bool pos = (labs[j] == 1);
            ce -= pos ? (a1[j] - lse) : (a0[j] - lse);
            float p1 = e1 / sum;
            sp += p1;
            msk[j] = 0.f;
            if (pos) { tp += p1; cnt += 1.f; nib |= (1u << j); msk[j] = 1.f; }
        }
        // pack pos bits: 8 lanes * 4 voxels = one 32-bit word
        unsigned part = nib << ((lane & 7) * 4);
        part |= __shfl_xor_sync(0xffffffffu, part, 1);
        part |= __shfl_xor_sync(0xffffffffu, part, 2);
        part |= __shfl_xor_sync(0xffffffffu, part, 4);
        if ((lane & 7) == 0) g_pos[v >> 5] = part;

        const float* fb = feat + (size_t)b * 32 * S_ + s;
#pragma unroll
        for (int c = 0; c < 32; c++) {
            const float4 f = *reinterpret_cast<const float4*>(fb + (size_t)c * S_);
            acc[c] += f.x * msk[0] + f.y * msk[1] + f.z * msk[2] + f.w * msk[3];
        }
    }

    // block reduction: warp butterfly -> shared -> atomics
#pragma unroll
    for (int c = 0; c < 32; c++) acc[c] = warpRed(acc[c]);
    ce = warpRed(ce); sp = warpRed(sp); tp = warpRed(tp); cnt = warpRed(cnt);

    __shared__ float sh[8][36];
    const int w = threadIdx.x >> 5;
    if (lane == 0) {
#pragma unroll
        for (int c = 0; c < 32; c++) sh[w][c] = acc[c];
        sh[w][32] = ce; sh[w][33] = sp; sh[w][34] = tp; sh[w][35] = cnt;
    }
    __syncthreads();
    if (threadIdx.x < 36) {
        float t = 0.f;
#pragma unroll
        for (int u = 0; u < 8; u++) t += sh[u][threadIdx.x];
        atomicAdd(&g_accA[threadIdx.x], t);
    }
}

// ---------------- 2: normalize std ----------------
__global__ void kA2() {
    int c = threadIdx.x;                // 32 threads
    float cnt = g_accA[35];
    float std = (cnt > 0.f) ? g_accA[c] / fmaxf(cnt, 1.f) : 0.f;
    float sq = std * std;
#pragma unroll
    for (int o = 16; o; o >>= 1) sq += __shfl_xor_sync(0xffffffffu, sq, o);
    float nrm = sqrtf(sq);
    g_stdn[c] = std / fmaxf(nrm, 1e-12f);
}

// ---------------- 3: sim pass (feature read #2, REVERSE order for L2 reuse) ----------------
// kA finished reading high addresses most recently -> L2 holds the tail.
// kB consumes quads in descending address order to hit that tail first.
__global__ __launch_bounds__(256) void kB(const float* __restrict__ feat) {
    __shared__ float ssn[32];
    if (threadIdx.x < 32) ssn[threadIdx.x] = g_stdn[threadIdx.x];
    __syncthreads();

    float psum = 0.f;
    const int stride = gridDim.x * blockDim.x;
    for (int i = blockIdx.x * blockDim.x + threadIdx.x; i < N_ / 4; i += stride) {
        const int q = (N_ / 4 - 1) - i;      // reversed quad index
        const int v = q << 2;
        const int b = v >> 20;
        const int s = v & (S_ - 1);
        const float* fb = feat + (size_t)b * 32 * S_ + s;

        float d0 = 0, d1 = 0, d2 = 0, d3 = 0, n0 = 0, n1 = 0, n2 = 0, n3 = 0;
#pragma unroll
        for (int c = 0; c < 32; c++) {
            const float4 f = *reinterpret_cast<const float4*>(fb + (size_t)c * S_);
            const float wc = ssn[c];
            d0 += f.x * wc; n0 += f.x * f.x;
            d1 += f.y * wc; n1 += f.y * f.y;
            d2 += f.z * wc; n2 += f.z * f.z;
            d3 += f.w * wc; n3 += f.w * f.w;
        }
        float sims[4];
        sims[0] = d0 / fmaxf(sqrtf(n0), 1e-12f);
        sims[1] = d1 / fmaxf(sqrtf(n1), 1e-12f);
        sims[2] = d2 / fmaxf(sqrtf(n2), 1e-12f);
        sims[3] = d3 / fmaxf(sqrtf(n3), 1e-12f);
        *reinterpret_cast<float4*>(g_sim + v) = make_float4(sims[0], sims[1], sims[2], sims[3]);

        const unsigned pw = g_pos[v >> 5];
        const unsigned base = v & 31;
#pragma unroll
        for (int j = 0; j < 4; j++) {
            bool pos = (pw >> (base + j)) & 1u;
            if (pos) {
                psum += 1.f - sims[j];
            } else {
                int bin = (int)((sims[j] + 1.0f) * 2048.0f);
                bin = max(0, min(4095, bin));
                atomicAdd(&g_hist[bin], 1);
            }
        }
    }
    psum = warpRed(psum);
    __shared__ float shp[8];
    if ((threadIdx.x & 31) == 0) shp[threadIdx.x >> 5] = psum;
    __syncthreads();
    if (threadIdx.x == 0) {
        float t = 0.f;
#pragma unroll
        for (int u = 0; u < 8; u++) t += shp[u];
        atomicAdd(&g_possum, t);
    }
}

// ---------------- bit-packed separable Chebyshev-10 dilation ----------------
__global__ void kDilW(int which) {      // in (pos|hsm) -> g_t1
    const unsigned* in = which ? g_hsm : g_pos;
    int r = blockIdx.x * blockDim.x + threadIdx.x;
    if (r >= NROWS_) return;
    unsigned a0 = in[r * 4 + 0], a1 = in[r * 4 + 1], a2 = in[r * 4 + 2], a3 = in[r * 4 + 3];
    unsigned c0 = a0, c1 = a1, c2 = a2, c3 = a3;
#pragma unroll
    for (int s = 1; s <= 10; s++) {
        c0 |= (a0 << s) | __funnelshift_r(a0, a1, s);
        c1 |= __funnelshift_l(a0, a1, s) | __funnelshift_r(a1, a2, s);
        c2 |= __funnelshift_l(a1, a2, s) | __funnelshift_r(a2, a3, s);
        c3 |= __funnelshift_l(a2, a3, s) | (a3 >> s);
    }
    g_t1[r * 4 + 0] = c0; g_t1[r * 4 + 1] = c1; g_t1[r * 4 + 2] = c2; g_t1[r * 4 + 3] = c3;
}

__global__ void kDilH() {               // g_t1 -> g_t2
    int w = blockIdx.x * blockDim.x + threadIdx.x;
    if (w >= NW_) return;
    int k = w & 3, h = (w >> 2) & 127, base = (w >> 9) << 9;
    int h0 = max(h - 10, 0), h1 = min(h + 10, 127);
    unsigned acc = 0u;
    for (int hh = h0; hh <= h1; hh++) acc |= g_t1[base + (hh << 2) + k];
    g_t2[w] = acc;
}

__global__ void kDilD(int which) {      // g_t2 -> (dilP|dilH)
    int w = blockIdx.x * blockDim.x + threadIdx.x;
    if (w >= NW_) return;
    int j = w & 511, d = (w >> 9) & 63, base = (w >> 15) << 15;
    int d0 = max(d - 10, 0), d1 = min(d + 10, 63);
    unsigned acc = 0u;
    for (int dd = d0; dd <= d1; dd++) acc |= g_t2[base + (dd << 9) + j];
    (which ? g_dilH : g_dilP)[w] = acc;
}

// ---------------- top-k threshold bin via suffix scan ----------------
__global__ void kT1() {
    __shared__ int shh[4096];
    __shared__ int ssum[1024];
    int t = threadIdx.x;
#pragma unroll
    for (int k = 0; k < 4; k++) shh[t * 4 + k] = g_hist[t * 4 + k];
    __syncthreads();
    ssum[t] = shh[t * 4] + shh[t * 4 + 1] + shh[t * 4 + 2] + shh[t * 4 + 3];
    __syncthreads();
    for (int off = 1; off < 1024; off <<= 1) {
        int add = (t + off < 1024) ? ssum[t + off] : 0;
        __syncthreads();
        ssum[t] += add;
        __syncthreads();
    }
    int run = (t < 1023) ? ssum[t + 1] : 0;   // suffix count strictly below this chunk's bins
    for (int k = 3; k >= 0; k--) {
        int nr = run + shh[t * 4 + k];
        if (run < TOPN && nr >= TOPN) g_bstar = t * 4 + k;  // exactly one thread writes
        run = nr;
    }
}

// ---------------- gather candidates >= threshold bin ----------------
__global__ void kG() {
    const int stride = gridDim.x * blockDim.x;
    const int bstar = g_bstar;
    for (int i = blockIdx.x * blockDim.x + threadIdx.x; i < N_ / 4; i += stride) {
        const int v = i << 2;
        const unsigned pw = g_pos[v >> 5];
        const float4 sm = *reinterpret_cast<const float4*>(g_sim + v);
        float sims[4] = {sm.x, sm.y, sm.z, sm.w};
        const unsigned base = v & 31;
#pragma unroll
        for (int j = 0; j < 4; j++) {
            bool pos = (pw >> (base + j)) & 1u;
            if (!pos) {
                int bin = (int)((sims[j] + 1.0f) * 2048.0f);
                bin = max(0, min(4095, bin));
                if (bin >= bstar) {
                    int id = atomicAdd(&g_ccount, 1);
                    if (id < CAPC) { g_cval[id] = sims[j]; g_cidx[id] = v + j; }
                }
            }
        }
    }
}

// ---------------- exact top-250 selection (top_k tie-break: value desc, index asc) ----------------
__global__ void kS() {
    __shared__ float sv[CAPC];
    __shared__ int   si[CAPC];
    int K = g_ccount; if (K > CAPC) K = CAPC;
    for (int i = threadIdx.x; i < K; i += blockDim.x) { sv[i] = g_cval[i]; si[i] = g_cidx[i]; }
    __syncthreads();
    for (int i = threadIdx.x; i < K; i += blockDim.x) {
        float v = sv[i]; int id = si[i];
        int rank = 0;
        for (int j = 0; j < K; j++) {
            float vj = sv[j];
            rank += (vj > v) || (vj == v && si[j] < id);
        }
        if (rank < TOPN) atomicOr(&g_hsm[id >> 5], 1u << (id & 31));
    }
}

// ---------------- mis + fin accumulation ----------------
__global__ __launch_bounds__(256) void kF() {
    float ms = 0.f, mc = 0.f, fs = 0.f, fc = 0.f;
    const int stride = gridDim.x * blockDim.x;
    for (int i = blockIdx.x * blockDim.x + threadIdx.x; i < N_ / 4; i += stride) {
        const int v = i << 2;
        const unsigned pw = g_pos[v >> 5], dp = g_dilP[v >> 5], dh = g_dilH[v >> 5];
        const float4 sm = *reinterpret_cast<const float4*>(g_sim + v);
        float sims[4] = {sm.x, sm.y, sm.z, sm.w};
        const unsigned base = v & 31;
#pragma unroll
        for (int j = 0; j < 4; j++) {
            unsigned bit = base + j;
            bool pos = (pw >> bit) & 1u;
            float r = fmaxf(sims[j], 0.f);
            if (((dp >> bit) & 1u) && !pos) { ms += r; mc += 1.f; }
            if (((dh >> bit) & 1u) && !pos) { fs += r; fc += 1.f; }
        }
    }
    ms = warpRed(ms); mc = warpRed(mc); fs = warpRed(fs); fc = warpRed(fc);
    __shared__ float sh4[8][4];
    if ((threadIdx.x & 31) == 0) {
        int w = threadIdx.x >> 5;
        sh4[w][0] = ms; sh4[w][1] = mc; sh4[w][2] = fs; sh4[w][3] = fc;
    }
    __syncthreads();
    if (threadIdx.x < 4) {
        float t = 0.f;
#pragma unroll
        for (int u = 0; u < 8; u++) t += sh4[u][threadIdx.x];
        if      (threadIdx.x == 0) atomicAdd(&g_msum, t);
        else if (threadIdx.x == 1) atomicAdd(&g_mcnt, t);
        else if (threadIdx.x == 2) atomicAdd(&g_fsum, t);
        else                       atomicAdd(&g_fcnt, t);
    }
}

// ---------------- final combine ----------------
__global__ void kZ(float* __restrict__ out) {
    const float Nf = (float)N_;
    float ce  = g_accA[32] / Nf;
    float sp  = g_accA[33], tp = g_accA[34], cnt = g_accA[35];
    float dc  = (2.f * tp + 1e-5f) / (sp + cnt + 1e-5f + 1e-8f);
    float dice = -dc;
    float pl = (cnt    > 0.f) ? g_possum / fmaxf(cnt,    1.f) : 0.f;
    float ml = (g_mcnt > 0.f) ? g_msum   / fmaxf(g_mcnt, 1.f) : 0.f;
    float nl = (g_fcnt > 0.f) ? g_fsum   / fmaxf(g_fcnt, 1.f) : 0.f;
    out[0] = ce + dice + 5.f * (pl + ml + nl);
}

// ---------------- launch ----------------
extern "C" void kernel_launch(void* const* d_in, const int* in_sizes, int n_in,
                              void* d_out, int out_size) {
    const float* feat = (const float*)d_in[0];
    const float* net  = (const float*)d_in[1];
    const int*   tgt  = (const int*)d_in[2];
    float* out = (float*)d_out;

    kInit<<<256, 256>>>();
    kA<<<1024, 256>>>(feat, net, tgt);
    kA2<<<1, 32>>>();
    kB<<<1024, 256>>>(feat);

    // dilate pos mask
    kDilW<<<64, 256>>>(0);
    kDilH<<<256, 256>>>();
    kDilD<<<256, 256>>>(0);

    // exact top-250 of neg sims
    kT1<<<1, 1024>>>();
    kG<<<256, 256>>>();
    kS<<<1, 256>>>();

    // dilate hsm mask
    kDilW<<<64, 256>>>(1);
    kDilH<<<256, 256>>>();
    kDilD<<<256, 256>>>(1);

    kF<<<512, 256>>>();
    kZ<<<1, 1>>>(out);
}

// round 10
// speedup vs baseline: 1.5346x; 1.3314x over previous
#include <cuda_runtime.h>
#include <cuda_bf16.h>

// Shapes (fixed by the problem)
#define S_      (1 << 20)           // D*H*W = 64*128*128
#define N_      (1 << 21)           // B * S_
#define NW_     (N_ / 32)           // 65536 mask words
#define NROWS_  (N_ / 128)          // 16384 W-rows
#define CAPC    4096
#define TOPN    250

// ---------------- device scratch (static; no allocations) ----------------
__device__ float    g_sim[N_];                      // 8 MB
__device__ unsigned g_pos[NW_], g_t1[NW_], g_t2[NW_];
__device__ unsigned g_dilP[NW_], g_hsm[NW_], g_dilH[NW_];
__device__ int      g_hist[4096];
__device__ int      g_bstar;
__device__ int      g_ccount;
__device__ float    g_cval[CAPC];
__device__ int      g_cidx[CAPC];
__device__ float    g_accA[36];   // [0..31] std sums, [32] ce, [33] sumP1, [34] tp1, [35] cnt(pos)
__device__ float    g_stdn[32];
__device__ float    g_possum, g_msum, g_mcnt, g_fsum, g_fcnt;

__device__ __forceinline__ float warpRed(float x) {
#pragma unroll
    for (int o = 16; o; o >>= 1) x += __shfl_xor_sync(0xffffffffu, x, o);
    return x;
}

// ---------------- 0: zero accumulators + hsm + hist ----------------
__global__ void kInit() {
    int i = blockIdx.x * blockDim.x + threadIdx.x;
    if (i < NW_)  g_hsm[i]  = 0u;
    if (i < 4096) g_hist[i] = 0;
    if (i < 36)   g_accA[i] = 0.f;
    if (i == 0) {
        g_bstar = 0; g_ccount = 0;
        g_possum = 0.f; g_msum = 0.f; g_mcnt = 0.f; g_fsum = 0.f; g_fcnt = 0.f;
    }
}

// ---------------- 1: fused stats pass (feature read #1) ----------------
// CE sum, sum(p1), tp1, pos count, per-channel masked feature sums, pos bitmask.
__global__ __launch_bounds__(256) void kA(const float* __restrict__ feat,
                                          const float* __restrict__ net,
                                          const int*   __restrict__ tgt) {
    float acc[32];
#pragma unroll
    for (int c = 0; c < 32; c++) acc[c] = 0.f;
    float ce = 0.f, sp = 0.f, tp = 0.f, cnt = 0.f;
    const int lane = threadIdx.x & 31;
    const int stride = gridDim.x * blockDim.x;

    for (int i = blockIdx.x * blockDim.x + threadIdx.x; i < N_ / 4; i += stride) {
        const int v = i << 2;
        const int b = v >> 20;
        const int s = v & (S_ - 1);

        const int4 lb = *reinterpret_cast<const int4*>(tgt + v);
        const float* nb = net + (size_t)b * 2 * S_ + s;
        const float4 x0 = *reinterpret_cast<const float4*>(nb);
        const float4 x1 = *reinterpret_cast<const float4*>(nb + S_);

        float a0[4] = {x0.x, x0.y, x0.z, x0.w};
        float a1[4] = {x1.x, x1.y, x1.z, x1.w};
        int   labs[4] = {lb.x, lb.y, lb.z, lb.w};
        float msk[4];
        unsigned nib = 0u;
#pragma unroll
        for (int j = 0; j < 4; j++) {
            float m  = fmaxf(a0[j], a1[j]);
            float e0 = __expf(a0[j] - m), e1 = __expf(a1[j] - m);
            float sum = e0 + e1;
            float lse = m + __logf(sum);
            bool pos = (labs[j] == 1);
            ce -= pos ? (a1[j] - lse) : (a0[j] - lse);
            float p1 = e1 / sum;
            sp += p1;
            msk[j] = 0.f;
            if (pos) { tp += p1; cnt += 1.f; nib |= (1u << j); msk[j] = 1.f; }
        }
        // pack pos bits: 8 lanes * 4 voxels = one 32-bit word
        unsigned part = nib << ((lane & 7) * 4);
        part |= __shfl_xor_sync(0xffffffffu, part, 1);
        part |= __shfl_xor_sync(0xffffffffu, part, 2);
        part |= __shfl_xor_sync(0xffffffffu, part, 4);
        if ((lane & 7) == 0) g_pos[v >> 5] = part;

        const float* fb = feat + (size_t)b * 32 * S_ + s;
#pragma unroll
        for (int c = 0; c < 32; c++) {
            const float4 f = *reinterpret_cast<const float4*>(fb + (size_t)c * S_);
            acc[c] += f.x * msk[0] + f.y * msk[1] + f.z * msk[2] + f.w * msk[3];
        }
    }

    // block reduction: warp butterfly -> shared -> atomics
#pragma unroll
    for (int c = 0; c < 32; c++) acc[c] = warpRed(acc[c]);
    ce = warpRed(ce); sp = warpRed(sp); tp = warpRed(tp); cnt = warpRed(cnt);

    __shared__ float sh[8][36];
    const int w = threadIdx.x >> 5;
    if (lane == 0) {
#pragma unroll
        for (int c = 0; c < 32; c++) sh[w][c] = acc[c];
        sh[w][32] = ce; sh[w][33] = sp; sh[w][34] = tp; sh[w][35] = cnt;
    }
    __syncthreads();
    if (threadIdx.x < 36) {
        float t = 0.f;
#pragma unroll
        for (int u = 0; u < 8; u++) t += sh[u][threadIdx.x];
        atomicAdd(&g_accA[threadIdx.x], t);
    }
}

// ---------------- 2: normalize std ----------------
__global__ void kA2() {
    int c = threadIdx.x;                // 32 threads
    float cnt = g_accA[35];
    float std = (cnt > 0.f) ? g_accA[c] / fmaxf(cnt, 1.f) : 0.f;
    float sq = std * std;
#pragma unroll
    for (int o = 16; o; o >>= 1) sq += __shfl_xor_sync(0xffffffffu, sq, o);
    float nrm = sqrtf(sq);
    g_stdn[c] = std / fmaxf(nrm, 1e-12f);
}

// ---------------- 3: sim pass (feature read #2) + pos_loss + SMEM histogram ----------------
// Histogram now lives in shared memory (16 KB), flushed once per block at the
// end; g_sim stores use streaming (evict-first) hint. Reverse iteration kept.
__global__ __launch_bounds__(256) void kB(const float* __restrict__ feat) {
    __shared__ float ssn[32];
    __shared__ int   shist[4096];
    if (threadIdx.x < 32) ssn[threadIdx.x] = g_stdn[threadIdx.x];
#pragma unroll
    for (int k = 0; k < 16; k++) shist[threadIdx.x + (k << 8)] = 0;
    __syncthreads();

    float psum = 0.f;
    const int stride = gridDim.x * blockDim.x;
    for (int i = blockIdx.x * blockDim.x + threadIdx.x; i < N_ / 4; i += stride) {
        const int q = (N_ / 4 - 1) - i;      // reversed quad index
        const int v = q << 2;
        const int b = v >> 20;
        const int s = v & (S_ - 1);
        const float* fb = feat + (size_t)b * 32 * S_ + s;

        float d0 = 0, d1 = 0, d2 = 0, d3 = 0, n0 = 0, n1 = 0, n2 = 0, n3 = 0;
#pragma unroll
        for (int c = 0; c < 32; c++) {
            const float4 f = *reinterpret_cast<const float4*>(fb + (size_t)c * S_);
            const float wc = ssn[c];
            d0 += f.x * wc; n0 += f.x * f.x;
            d1 += f.y * wc; n1 += f.y * f.y;
            d2 += f.z * wc; n2 += f.z * f.z;
            d3 += f.w * wc; n3 += f.w * f.w;
        }
        float sims[4];
        sims[0] = d0 / fmaxf(sqrtf(n0), 1e-12f);
        sims[1] = d1 / fmaxf(sqrtf(n1), 1e-12f);
        sims[2] = d2 / fmaxf(sqrtf(n2), 1e-12f);
        sims[3] = d3 / fmaxf(sqrtf(n3), 1e-12f);
        __stcs(reinterpret_cast<float4*>(g_sim + v),
               make_float4(sims[0], sims[1], sims[2], sims[3]));

        const unsigned pw = g_pos[v >> 5];
        const unsigned base = v & 31;
#pragma unroll
        for (int j = 0; j < 4; j++) {
            bool pos = (pw >> (base + j)) & 1u;
            if (pos) {
                psum += 1.f - sims[j];
            } else {
                int bin = (int)((sims[j] + 1.0f) * 2048.0f);
                bin = max(0, min(4095, bin));
                atomicAdd(&shist[bin], 1);
            }
        }
    }
    psum = warpRed(psum);
    __shared__ float shp[8];
    if ((threadIdx.x & 31) == 0) shp[threadIdx.x >> 5] = psum;
    __syncthreads();
    if (threadIdx.x == 0) {
        float t = 0.f;
#pragma unroll
        for (int u = 0; u < 8; u++) t += shp[u];
        atomicAdd(&g_possum, t);
    }
    // flush non-zero histogram bins
#pragma unroll
    for (int k = 0; k < 16; k++) {
        const int bin = threadIdx.x + (k << 8);
        const int val = shist[bin];
        if (val) atomicAdd(&g_hist[bin], val);
    }
}

// ---------------- bit-packed separable Chebyshev-10 dilation ----------------
__global__ void kDilW(int which) {      // in (pos|hsm) -> g_t1
    const unsigned* in = which ? g_hsm : g_pos;
    int r = blockIdx.x * blockDim.x + threadIdx.x;
    if (r >= NROWS_) return;
    unsigned a0 = in[r * 4 + 0], a1 = in[r * 4 + 1], a2 = in[r * 4 + 2], a3 = in[r * 4 + 3];
    unsigned c0 = a0, c1 = a1, c2 = a2, c3 = a3;
#pragma unroll
    for (int s = 1; s <= 10; s++) {
        c0 |= (a0 << s) | __funnelshift_r(a0, a1, s);
        c1 |= __funnelshift_l(a0, a1, s) | __funnelshift_r(a1, a2, s);
        c2 |= __funnelshift_l(a1, a2, s) | __funnelshift_r(a2, a3, s);
        c3 |= __funnelshift_l(a2, a3, s) | (a3 >> s);
    }
    g_t1[r * 4 + 0] = c0; g_t1[r * 4 + 1] = c1; g_t1[r * 4 + 2] = c2; g_t1[r * 4 + 3] = c3;
}

__global__ void kDilH() {               // g_t1 -> g_t2
    int w = blockIdx.x * blockDim.x + threadIdx.x;
    if (w >= NW_) return;
    int k = w & 3, h = (w >> 2) & 127, base = (w >> 9) << 9;
    int h0 = max(h - 10, 0), h1 = min(h + 10, 127);
    unsigned acc = 0u;
    for (int hh = h0; hh <= h1; hh++) acc |= g_t1[base + (hh << 2) + k];
    g_t2[w] = acc;
}

__global__ void kDilD(int which) {      // g_t2 -> (dilP|dilH)
    int w = blockIdx.x * blockDim.x + threadIdx.x;
    if (w >= NW_) return;
    int j = w & 511, d = (w >> 9) & 63, base = (w >> 15) << 15;
    int d0 = max(d - 10, 0), d1 = min(d + 10, 63);
    unsigned acc = 0u;
    for (int dd = d0; dd <= d1; dd++) acc |= g_t2[base + (dd << 9) + j];
    (which ? g_dilH : g_dilP)[w] = acc;
}

// ---------------- top-k threshold bin via suffix scan ----------------
__global__ void kT1() {
    __shared__ int shh[4096];
    __shared__ int ssum[1024];
    int t = threadIdx.x;
#pragma unroll
    for (int k = 0; k < 4; k++) shh[t * 4 + k] = g_hist[t * 4 + k];
    __syncthreads();
    ssum[t] = shh[t * 4] + shh[t * 4 + 1] + shh[t * 4 + 2] + shh[t * 4 + 3];
    __syncthreads();
    for (int off = 1; off < 1024; off <<= 1) {
        int add = (t + off < 1024) ? ssum[t + off] : 0;
        __syncthreads();
        ssum[t] += add;
        __syncthreads();
    }
    int run = (t < 1023) ? ssum[t + 1] : 0;   // suffix count strictly below this chunk's bins
    for (int k = 3; k >= 0; k--) {
        int nr = run + shh[t * 4 + k];
        if (run < TOPN && nr >= TOPN) g_bstar = t * 4 + k;  // exactly one thread writes
        run = nr;
    }
}

// ---------------- gather candidates >= threshold bin ----------------
__global__ void kG() {
    const int stride = gridDim.x * blockDim.x;
    const int bstar = g_bstar;
    for (int i = blockIdx.x * blockDim.x + threadIdx.x; i < N_ / 4; i += stride) {
        const int v = i << 2;
        const unsigned pw = g_pos[v >> 5];
        const float4 sm = *reinterpret_cast<const float4*>(g_sim + v);
        float sims[4] = {sm.x, sm.y, sm.z, sm.w};
        const unsigned base = v & 31;
#pragma unroll
        for (int j = 0; j < 4; j++) {
            bool pos = (pw >> (base + j)) & 1u;
            if (!pos) {
                int bin = (int)((sims[j] + 1.0f) * 2048.0f);
                bin = max(0, min(4095, bin));
                if (bin >= bstar) {
                    int id = atomicAdd(&g_ccount, 1);
                    if (id < CAPC) { g_cval[id] = sims[j]; g_cidx[id] = v + j; }
                }
            }
        }
    }
}

// ---------------- exact top-250 selection (top_k tie-break: value desc, index asc) ----------------
__global__ void kS() {
    __shared__ float sv[CAPC];
    __shared__ int   si[CAPC];
    int K = g_ccount; if (K > CAPC) K = CAPC;
    for (int i = threadIdx.x; i < K; i += blockDim.x) { sv[i] = g_cval[i]; si[i] = g_cidx[i]; }
    __syncthreads();
    for (int i = threadIdx.x; i < K; i += blockDim.x) {
        float v = sv[i]; int id = si[i];
        int rank = 0;
        for (int j = 0; j < K; j++) {
            float vj = sv[j];
            rank += (vj > v) || (vj == v && si[j] < id);
        }
        if (rank < TOPN) atomicOr(&g_hsm[id >> 5], 1u << (id & 31));
    }
}

// ---------------- mis + fin accumulation ----------------
__global__ __launch_bounds__(256) void kF() {
    float ms = 0.f, mc = 0.f, fs = 0.f, fc = 0.f;
    const int stride = gridDim.x * blockDim.x;
    for (int i = blockIdx.x * blockDim.x + threadIdx.x; i < N_ / 4; i += stride) {
        const int v = i << 2;
        const unsigned pw = g_pos[v >> 5], dp = g_dilP[v >> 5], dh = g_dilH[v >> 5];
        const float4 sm = *reinterpret_cast<const float4*>(g_sim + v);
        float sims[4] = {sm.x, sm.y, sm.z, sm.w};
        const unsigned base = v & 31;
#pragma unroll
        for (int j = 0; j < 4; j++) {
            unsigned bit = base + j;
            bool pos = (pw >> bit) & 1u;
            float r = fmaxf(sims[j], 0.f);
            if (((dp >> bit) & 1u) && !pos) { ms += r; mc += 1.f; }
            if (((dh >> bit) & 1u) && !pos) { fs += r; fc += 1.f; }
        }
    }
    ms = warpRed(ms); mc = warpRed(mc); fs = warpRed(fs); fc = warpRed(fc);
    __shared__ float sh4[8][4];
    if ((threadIdx.x & 31) == 0) {
        int w = threadIdx.x >> 5;
        sh4[w][0] = ms; sh4[w][1] = mc; sh4[w][2] = fs; sh4[w][3] = fc;
    }
    __syncthreads();
    if (threadIdx.x < 4) {
        float t = 0.f;
#pragma unroll
        for (int u = 0; u < 8; u++) t += sh4[u][threadIdx.x];
        if      (threadIdx.x == 0) atomicAdd(&g_msum, t);
        else if (threadIdx.x == 1) atomicAdd(&g_mcnt, t);
        else if (threadIdx.x == 2) atomicAdd(&g_fsum, t);
        else                       atomicAdd(&g_fcnt, t);
    }
}

// ---------------- final combine ----------------
__global__ void kZ(float* __restrict__ out) {
    const float Nf = (float)N_;
    float ce  = g_accA[32] / Nf;
    float sp  = g_accA[33], tp = g_accA[34], cnt = g_accA[35];
    float dc  = (2.f * tp + 1e-5f) / (sp + cnt + 1e-5f + 1e-8f);
    float dice = -dc;
    float pl = (cnt    > 0.f) ? g_possum / fmaxf(cnt,    1.f) : 0.f;
    float ml = (g_mcnt > 0.f) ? g_msum   / fmaxf(g_mcnt, 1.f) : 0.f;
    float nl = (g_fcnt > 0.f) ? g_fsum   / fmaxf(g_fcnt, 1.f) : 0.f;
    out[0] = ce + dice + 5.f * (pl + ml + nl);
}

// ---------------- launch ----------------
extern "C" void kernel_launch(void* const* d_in, const int* in_sizes, int n_in,
                              void* d_out, int out_size) {
    const float* feat = (const float*)d_in[0];
    const float* net  = (const float*)d_in[1];
    const int*   tgt  = (const int*)d_in[2];
    float* out = (float*)d_out;

    kInit<<<256, 256>>>();
    kA<<<1024, 256>>>(feat, net, tgt);
    kA2<<<1, 32>>>();
    kB<<<1024, 256>>>(feat);

    // dilate pos mask
    kDilW<<<64, 256>>>(0);
    kDilH<<<256, 256>>>();
    kDilD<<<256, 256>>>(0);

    // exact top-250 of neg sims
    kT1<<<1, 1024>>>();
    kG<<<256, 256>>>();
    kS<<<1, 256>>>();

    // dilate hsm mask
    kDilW<<<64, 256>>>(1);
    kDilH<<<256, 256>>>();
    kDilD<<<256, 256>>>(1);

    kF<<<512, 256>>>();
    kZ<<<1, 1>>>(out);
}

// round 11
// speedup vs baseline: 1.5658x; 1.0203x over previous
#include <cuda_runtime.h>
#include <cuda_bf16.h>

// Shapes (fixed by the problem)
#define S_      (1 << 20)           // D*H*W = 64*128*128
#define N_      (1 << 21)           // B * S_
#define NW_     (N_ / 32)           // 65536 mask words
#define NROWS_  (N_ / 128)          // 16384 W-rows
#define CAPC    4096
#define TOPN    250

// ---------------- device scratch (static; no allocations) ----------------
__device__ float    g_sim[N_];                      // 8 MB
__device__ unsigned g_pos[NW_], g_t1[NW_], g_t2[NW_];
__device__ unsigned g_dilP[NW_], g_hsm[NW_], g_dilH[NW_];
__device__ int      g_hist[4096];
__device__ int      g_bstar;
__device__ int      g_ccount;
__device__ float    g_cval[CAPC];
__device__ int      g_cidx[CAPC];
__device__ float    g_accA[36];   // [0..31] std sums, [32] ce, [33] sumP1, [34] tp1, [35] cnt(pos)
__device__ float    g_stdn[32];
__device__ float    g_possum, g_msum, g_mcnt, g_fsum, g_fcnt;

__device__ __forceinline__ float warpRed(float x) {
#pragma unroll
    for (int o = 16; o; o >>= 1) x += __shfl_xor_sync(0xffffffffu, x, o);
    return x;
}

// ---------------- 0: zero accumulators + hsm + hist ----------------
__global__ void kInit() {
    int i = blockIdx.x * blockDim.x + threadIdx.x;
    if (i < NW_)  g_hsm[i]  = 0u;
    if (i < 4096) g_hist[i] = 0;
    if (i < 36)   g_accA[i] = 0.f;
    if (i == 0) {
        g_bstar = 0; g_ccount = 0;
        g_possum = 0.f; g_msum = 0.f; g_mcnt = 0.f; g_fsum = 0.f; g_fcnt = 0.f;
    }
}

// ---------------- 1: fused stats pass (feature read #1) ----------------
// Lane-pair channel split: even lanes own channels 0..15, odd lanes 16..31,
// both lanes of a pair cover the same 4-voxel group. Even lanes also do
// CE/softmax/pos-packing for the group. (regs ~48, occ ~59%)
__global__ __launch_bounds__(256) void kA(const float* __restrict__ feat,
                                          const float* __restrict__ net,
                                          const int*   __restrict__ tgt) {
    float acc[16];
#pragma unroll
    for (int c = 0; c < 16; c++) acc[c] = 0.f;
    float ce = 0.f, sp = 0.f, tp = 0.f, cnt = 0.f;
    const int lane = threadIdx.x & 31;
    const int half = (lane & 1) << 4;            // channel offset: 0 or 16
    const int stride = gridDim.x * blockDim.x;   // even, so pair structure is preserved

    for (int g = blockIdx.x * blockDim.x + threadIdx.x; g < N_ / 2; g += stride) {
        const int gg = g >> 1;                   // voxel group index (4 voxels)
        const int v = gg << 2;
        const int b = v >> 20;
        const int s = v & (S_ - 1);

        unsigned nib = 0u;
        if (!(lane & 1)) {
            const int4 lb = *reinterpret_cast<const int4*>(tgt + v);
            const float* nb = net + (size_t)b * 2 * S_ + s;
            const float4 x0 = *reinterpret_cast<const float4*>(nb);
            const float4 x1 = *reinterpret_cast<const float4*>(nb + S_);
            float a0[4] = {x0.x, x0.y, x0.z, x0.w};
            float a1[4] = {x1.x, x1.y, x1.z, x1.w};
            int   labs[4] = {lb.x, lb.y, lb.z, lb.w};
#pragma unroll
            for (int j = 0; j < 4; j++) {
                float m  = fmaxf(a0[j], a1[j]);
                float e0 = __expf(a0[j] - m), e1 = __expf(a1[j] - m);
                float sum = e0 + e1;
                float lse = m + __logf(sum);
                bool pos = (labs[j] == 1);
                ce -= pos ? (a1[j] - lse) : (a0[j] - lse);
                float p1 = e1 / sum;
                sp += p1;
                if (pos) { tp += p1; cnt += 1.f; nib |= (1u << j); }
            }
        }
        // broadcast mask nibble from the even lane of the pair
        nib = __shfl_sync(0xffffffffu, nib, lane & ~1);
        const float m0 = (float)( nib       & 1u);
        const float m1 = (float)((nib >> 1) & 1u);
        const float m2 = (float)((nib >> 2) & 1u);
        const float m3 = (float)((nib >> 3) & 1u);

        const float* fb = feat + (size_t)b * 32 * S_ + (size_t)half * S_ + s;
#pragma unroll
        for (int c = 0; c < 16; c++) {
            const float4 f = *reinterpret_cast<const float4*>(fb + (size_t)c * S_);
            acc[c] += f.x * m0 + f.y * m1 + f.z * m2 + f.w * m3;
        }

        // pack pos bits: 8 pairs (even lanes) * 4 voxels = one 32-bit word per half-warp
        {
            unsigned part = nib << (((lane >> 1) & 7) * 4);
            part |= __shfl_xor_sync(0x55555555u, part, 2);
            part |= __shfl_xor_sync(0x55555555u, part, 4);
            part |= __shfl_xor_sync(0x55555555u, part, 8);
            if ((lane & 15) == 0) g_pos[v >> 5] = part;
        }
    }

    // parity-preserving warp reduction: lane0 holds channels 0..15, lane1 holds 16..31
#pragma unroll
    for (int c = 0; c < 16; c++) {
        acc[c] += __shfl_xor_sync(0xffffffffu, acc[c], 2);
        acc[c] += __shfl_xor_sync(0xffffffffu, acc[c], 4);
        acc[c] += __shfl_xor_sync(0xffffffffu, acc[c], 8);
        acc[c] += __shfl_xor_sync(0xffffffffu, acc[c], 16);
    }
    ce = warpRed(ce); sp = warpRed(sp); tp = warpRed(tp); cnt = warpRed(cnt);

    __shared__ float sh[8][36];
    const int w = threadIdx.x >> 5;
    if (lane < 2) {
#pragma unroll
        for (int c = 0; c < 16; c++) sh[w][half + c] = acc[c];
    }
    if (lane == 0) { sh[w][32] = ce; sh[w][33] = sp; sh[w][34] = tp; sh[w][35] = cnt; }
    __syncthreads();
    if (threadIdx.x < 36) {
        float t = 0.f;
#pragma unroll
        for (int u = 0; u < 8; u++) t += sh[u][threadIdx.x];
        atomicAdd(&g_accA[threadIdx.x], t);
    }
}

// ---------------- 2: normalize std ----------------
__global__ void kA2() {
    int c = threadIdx.x;                // 32 threads
    float cnt = g_accA[35];
    float std = (cnt > 0.f) ? g_accA[c] / fmaxf(cnt, 1.f) : 0.f;
    float sq = std * std;
#pragma unroll
    for (int o = 16; o; o >>= 1) sq += __shfl_xor_sync(0xffffffffu, sq, o);
    float nrm = sqrtf(sq);
    g_stdn[c] = std / fmaxf(nrm, 1e-12f);
}

// ---------------- 3: sim pass (feature read #2) + pos_loss + SMEM histogram ----------------
// Histogram in shared memory (16 KB), flushed once per block at the end;
// g_sim stores use streaming (evict-first) hint. Reverse iteration kept.
__global__ __launch_bounds__(256) void kB(const float* __restrict__ feat) {
    __shared__ float ssn[32];
    __shared__ int   shist[4096];
    if (threadIdx.x < 32) ssn[threadIdx.x] = g_stdn[threadIdx.x];
#pragma unroll
    for (int k = 0; k < 16; k++) shist[threadIdx.x + (k << 8)] = 0;
    __syncthreads();

    float psum = 0.f;
    const int stride = gridDim.x * blockDim.x;
    for (int i = blockIdx.x * blockDim.x + threadIdx.x; i < N_ / 4; i += stride) {
        const int q = (N_ / 4 - 1) - i;      // reversed quad index
        const int v = q << 2;
        const int b = v >> 20;
        const int s = v & (S_ - 1);
        const float* fb = feat + (size_t)b * 32 * S_ + s;

        float d0 = 0, d1 = 0, d2 = 0, d3 = 0, n0 = 0, n1 = 0, n2 = 0, n3 = 0;
#pragma unroll
        for (int c = 0; c < 32; c++) {
            const float4 f = *reinterpret_cast<const float4*>(fb + (size_t)c * S_);
            const float wc = ssn[c];
            d0 += f.x * wc; n0 += f.x * f.x;
            d1 += f.y * wc; n1 += f.y * f.y;
            d2 += f.z * wc; n2 += f.z * f.z;
            d3 += f.w * wc; n3 += f.w * f.w;
        }
        float sims[4];
        sims[0] = d0 / fmaxf(sqrtf(n0), 1e-12f);
        sims[1] = d1 / fmaxf(sqrtf(n1), 1e-12f);
        sims[2] = d2 / fmaxf(sqrtf(n2), 1e-12f);
        sims[3] = d3 / fmaxf(sqrtf(n3), 1e-12f);
        __stcs(reinterpret_cast<float4*>(g_sim + v),
               make_float4(sims[0], sims[1], sims[2], sims[3]));

        const unsigned pw = g_pos[v >> 5];
        const unsigned base = v & 31;
#pragma unroll
        for (int j = 0; j < 4; j++) {
            bool pos = (pw >> (base + j)) & 1u;
            if (pos) {
                psum += 1.f - sims[j];
            } else {
                int bin = (int)((sims[j] + 1.0f) * 2048.0f);
                bin = max(0, min(4095, bin));
                atomicAdd(&shist[bin], 1);
            }
        }
    }
    psum = warpRed(psum);
    __shared__ float shp[8];
    if ((threadIdx.x & 31) == 0) shp[threadIdx.x >> 5] = psum;
    __syncthreads();
    if (threadIdx.x == 0) {
        float t = 0.f;
#pragma unroll
        for (int u = 0; u < 8; u++) t += shp[u];
        atomicAdd(&g_possum, t);
    }
    // flush non-zero histogram bins
#pragma unroll
    for (int k = 0; k < 16; k++) {
        const int bin = threadIdx.x + (k << 8);
        const int val = shist[bin];
        if (val) atomicAdd(&g_hist[bin], val);
    }
}

// ---------------- bit-packed separable Chebyshev-10 dilation ----------------
__global__ void kDilW(int which) {      // in (pos|hsm) -> g_t1
    const unsigned* in = which ? g_hsm : g_pos;
    int r = blockIdx.x * blockDim.x + threadIdx.x;
    if (r >= NROWS_) return;
    unsigned a0 = in[r * 4 + 0], a1 = in[r * 4 + 1], a2 = in[r * 4 + 2], a3 = in[r * 4 + 3];
    unsigned c0 = a0, c1 = a1, c2 = a2, c3 = a3;
#pragma unroll
    for (int s = 1; s <= 10; s++) {
        c0 |= (a0 << s) | __funnelshift_r(a0, a1, s);
        c1 |= __funnelshift_l(a0, a1, s) | __funnelshift_r(a1, a2, s);
        c2 |= __funnelshift_l(a1, a2, s) | __funnelshift_r(a2, a3, s);
        c3 |= __funnelshift_l(a2, a3, s) | (a3 >> s);
    }
    g_t1[r * 4 + 0] = c0; g_t1[r * 4 + 1] = c1; g_t1[r * 4 + 2] = c2; g_t1[r * 4 + 3] = c3;
}

__global__ void kDilH() {               // g_t1 -> g_t2
    int w = blockIdx.x * blockDim.x + threadIdx.x;
    if (w >= NW_) return;
    int k = w & 3, h = (w >> 2) & 127, base = (w >> 9) << 9;
    int h0 = max(h - 10, 0), h1 = min(h + 10, 127);
    unsigned acc = 0u;
    for (int hh = h0; hh <= h1; hh++) acc |= g_t1[base + (hh << 2) + k];
    g_t2[w] = acc;
}

__global__ void kDilD(int which) {      // g_t2 -> (dilP|dilH)
    int w = blockIdx.x * blockDim.x + threadIdx.x;
    if (w >= NW_) return;
    int j = w & 511, d = (w >> 9) & 63, base = (w >> 15) << 15;
    int d0 = max(d - 10, 0), d1 = min(d + 10, 63);
    unsigned acc = 0u;
    for (int dd = d0; dd <= d1; dd++) acc |= g_t2[base + (dd << 9) + j];
    (which ? g_dilH : g_dilP)[w] = acc;
}

// ---------------- top-k threshold bin via suffix scan ----------------
__global__ void kT1() {
    __shared__ int shh[4096];
    __shared__ int ssum[1024];
    int t = threadIdx.x;
#pragma unroll
    for (int k = 0; k < 4; k++) shh[t * 4 + k] = g_hist[t * 4 + k];
    __syncthreads();
    ssum[t] = shh[t * 4] + shh[t * 4 + 1] + shh[t * 4 + 2] + shh[t * 4 + 3];
    __syncthreads();
    for (int off = 1; off < 1024; off <<= 1) {
        int add = (t + off < 1024) ? ssum[t + off] : 0;
        __syncthreads();
        ssum[t] += add;
        __syncthreads();
    }
    int run = (t < 1023) ? ssum[t + 1] : 0;   // suffix count strictly below this chunk's bins
    for (int k = 3; k >= 0; k--) {
        int nr = run + shh[t * 4 + k];
        if (run < TOPN && nr >= TOPN) g_bstar = t * 4 + k;  // exactly one thread writes
        run = nr;
    }
}

// ---------------- gather candidates >= threshold bin ----------------
__global__ void kG() {
    const int stride = gridDim.x * blockDim.x;
    const int bstar = g_bstar;
    for (int i = blockIdx.x * blockDim.x + threadIdx.x; i < N_ / 4; i += stride) {
        const int v = i << 2;
        const unsigned pw = g_pos[v >> 5];
        const float4 sm = *reinterpret_cast<const float4*>(g_sim + v);
        float sims[4] = {sm.x, sm.y, sm.z, sm.w};
        const unsigned base = v & 31;
#pragma unroll
        for (int j = 0; j < 4; j++) {
            bool pos = (pw >> (base + j)) & 1u;
            if (!pos) {
                int bin = (int)((sims[j] + 1.0f) * 2048.0f);
                bin = max(0, min(4095, bin));
                if (bin >= bstar) {
                    int id = atomicAdd(&g_ccount, 1);
                    if (id < CAPC) { g_cval[id] = sims[j]; g_cidx[id] = v + j; }
                }
            }
        }
    }
}

// ---------------- exact top-250 selection (top_k tie-break: value desc, index asc) ----------------
__global__ void kS() {
    __shared__ float sv[CAPC];
    __shared__ int   si[CAPC];
    int K = g_ccount; if (K > CAPC) K = CAPC;
    for (int i = threadIdx.x; i < K; i += blockDim.x) { sv[i] = g_cval[i]; si[i] = g_cidx[i]; }
    __syncthreads();
    for (int i = threadIdx.x; i < K; i += blockDim.x) {
        float v = sv[i]; int id = si[i];
        int rank = 0;
        for (int j = 0; j < K; j++) {
            float vj = sv[j];
            rank += (vj > v) || (vj == v && si[j] < id);
        }
        if (rank < TOPN) atomicOr(&g_hsm[id >> 5], 1u << (id & 31));
    }
}

// ---------------- mis + fin accumulation ----------------
__global__ __launch_bounds__(256) void kF() {
    float ms = 0.f, mc = 0.f, fs = 0.f, fc = 0.f;
    const int stride = gridDim.x * blockDim.x;
    for (int i = blockIdx.x * blockDim.x + threadIdx.x; i < N_ / 4; i += stride) {
        const int v = i << 2;
        const unsigned pw = g_pos[v >> 5], dp = g_dilP[v >> 5], dh = g_dilH[v >> 5];
        const float4 sm = *reinterpret_cast<const float4*>(g_sim + v);
        float sims[4] = {sm.x, sm.y, sm.z, sm.w};
        const unsigned base = v & 31;
#pragma unroll
        for (int j = 0; j < 4; j++) {
            unsigned bit = base + j;
            bool pos = (pw >> bit) & 1u;
            float r = fmaxf(sims[j], 0.f);
            if (((dp >> bit) & 1u) && !pos) { ms += r; mc += 1.f; }
            if (((dh >> bit) & 1u) && !pos) { fs += r; fc += 1.f; }
        }
    }
    ms = warpRed(ms); mc = warpRed(mc); fs = warpRed(fs); fc = warpRed(fc);
    __shared__ float sh4[8][4];
    if ((threadIdx.x & 31) == 0) {
        int w = threadIdx.x >> 5;
        sh4[w][0] = ms; sh4[w][1] = mc; sh4[w][2] = fs; sh4[w][3] = fc;
    }
    __syncthreads();
    if (threadIdx.x < 4) {
        float t = 0.f;
#pragma unroll
        for (int u = 0; u < 8; u++) t += sh4[u][threadIdx.x];
        if      (threadIdx.x == 0) atomicAdd(&g_msum, t);
        else if (threadIdx.x == 1) atomicAdd(&g_mcnt, t);
        else if (threadIdx.x == 2) atomicAdd(&g_fsum, t);
        else                       atomicAdd(&g_fcnt, t);
    }
}

// ---------------- final combine ----------------
__global__ void kZ(float* __restrict__ out) {
    const float Nf = (float)N_;
    float ce  = g_accA[32] / Nf;
    float sp  = g_accA[33], tp = g_accA[34], cnt = g_accA[35];
    float dc  = (2.f * tp + 1e-5f) / (sp + cnt + 1e-5f + 1e-8f);
    float dice = -dc;
    float pl = (cnt    > 0.f) ? g_possum / fmaxf(cnt,    1.f) : 0.f;
    float ml = (g_mcnt > 0.f) ? g_msum   / fmaxf(g_mcnt, 1.f) : 0.f;
    float nl = (g_fcnt > 0.f) ? g_fsum   / fmaxf(g_fcnt, 1.f) : 0.f;
    out[0] = ce + dice + 5.f * (pl + ml + nl);
}

// ---------------- launch ----------------
extern "C" void kernel_launch(void* const* d_in, const int* in_sizes, int n_in,
                              void* d_out, int out_size) {
    const float* feat = (const float*)d_in[0];
    const float* net  = (const float*)d_in[1];
    const int*   tgt  = (const int*)d_in[2];
    float* out = (float*)d_out;

    kInit<<<256, 256>>>();
    kA<<<2048, 256>>>(feat, net, tgt);
    kA2<<<1, 32>>>();
    kB<<<1024, 256>>>(feat);

    // dilate pos mask
    kDilW<<<64, 256>>>(0);
    kDilH<<<256, 256>>>();
    kDilD<<<256, 256>>>(0);

    // exact top-250 of neg sims
    kT1<<<1, 1024>>>();
    kG<<<256, 256>>>();
    kS<<<1, 256>>>();

    // dilate hsm mask
    kDilW<<<64, 256>>>(1);
    kDilH<<<256, 256>>>();
    kDilD<<<256, 256>>>(1);

    kF<<<512, 256>>>();
    kZ<<<1, 1>>>(out);
}

// round 17
// speedup vs baseline: 1.5803x; 1.0093x over previous
#include <cuda_runtime.h>
#include <cuda_bf16.h>

// Shapes (fixed by the problem)
#define S_      (1 << 20)           // D*H*W = 64*128*128
#define N_      (1 << 21)           // B * S_
#define NW_     (N_ / 32)           // 65536 mask words
#define NROWS_  (N_ / 128)          // 16384 W-rows
#define CAPC    4096
#define TOPN    250

// ---------------- device scratch (static; no allocations) ----------------
__device__ float    g_sim[N_];                      // 8 MB
__device__ unsigned g_pos[NW_], g_t1[NW_], g_t2[NW_];
__device__ unsigned g_dilP[NW_], g_dilH[NW_];
__device__ int      g_hist[4096];
__device__ int      g_bstar;
__device__ int      g_ccount;
__device__ float    g_cval[CAPC];
__device__ int      g_cidx[CAPC];
__device__ float    g_accA[36];   // [0..31] std sums, [32] ce, [33] sumP1, [34] tp1, [35] cnt(pos)
__device__ float    g_stdn[32];
__device__ float    g_possum, g_msum, g_mcnt, g_fsum, g_fcnt;

__device__ __forceinline__ float warpRed(float x) {
#pragma unroll
    for (int o = 16; o; o >>= 1) x += __shfl_xor_sync(0xffffffffu, x, o);
    return x;
}

// ---------------- 0: zero accumulators + dilH + hist ----------------
__global__ void kInit() {
    int i = blockIdx.x * blockDim.x + threadIdx.x;
    if (i < NW_)  g_dilH[i] = 0u;                 // scatter-dilation target
    if (i < 4096) g_hist[i] = 0;
    if (i < 36)   g_accA[i] = 0.f;
    if (i == 0) {
        g_bstar = 0; g_ccount = 0;
        g_possum = 0.f; g_msum = 0.f; g_mcnt = 0.f; g_fsum = 0.f; g_fcnt = 0.f;
    }
}

// ---------------- 1: fused stats pass (feature read #1) ----------------
// Lane-pair channel split: even lanes own channels 0..15, odd lanes 16..31.
__global__ __launch_bounds__(256) void kA(const float* __restrict__ feat,
                                          const float* __restrict__ net,
                                          const int*   __restrict__ tgt) {
    float acc[16];
#pragma unroll
    for (int c = 0; c < 16; c++) acc[c] = 0.f;
    float ce = 0.f, sp = 0.f, tp = 0.f, cnt = 0.f;
    const int lane = threadIdx.x & 31;
    const int half = (lane & 1) << 4;            // channel offset: 0 or 16
    const int stride = gridDim.x * blockDim.x;

    for (int g = blockIdx.x * blockDim.x + threadIdx.x; g < N_ / 2; g += stride) {
        const int gg = g >> 1;                   // voxel group index (4 voxels)
        const int v = gg << 2;
        const int b = v >> 20;
        const int s = v & (S_ - 1);

        unsigned nib = 0u;
        if (!(lane & 1)) {
            const int4 lb = *reinterpret_cast<const int4*>(tgt + v);
            const float* nb = net + (size_t)b * 2 * S_ + s;
            const float4 x0 = *reinterpret_cast<const float4*>(nb);
            const float4 x1 = *reinterpret_cast<const float4*>(nb + S_);
            float a0[4] = {x0.x, x0.y, x0.z, x0.w};
            float a1[4] = {x1.x, x1.y, x1.z, x1.w};
            int   labs[4] = {lb.x, lb.y, lb.z, lb.w};
#pragma unroll
            for (int j = 0; j < 4; j++) {
                float m  = fmaxf(a0[j], a1[j]);
                float e0 = __expf(a0[j] - m), e1 = __expf(a1[j] - m);
                float sum = e0 + e1;
                float lse = m + __logf(sum);
                bool pos = (labs[j] == 1);
                ce -= pos ? (a1[j] - lse) : (a0[j] - lse);
                float p1 = e1 / sum;
                sp += p1;
                if (pos) { tp += p1; cnt += 1.f; nib |= (1u << j); }
            }
        }
        nib = __shfl_sync(0xffffffffu, nib, lane & ~1);
        const float m0 = (float)( nib       & 1u);
        const float m1 = (float)((nib >> 1) & 1u);
        const float m2 = (float)((nib >> 2) & 1u);
        const float m3 = (float)((nib >> 3) & 1u);

        const float* fb = feat + (size_t)b * 32 * S_ + (size_t)half * S_ + s;
#pragma unroll
        for (int c = 0; c < 16; c++) {
            const float4 f = *reinterpret_cast<const float4*>(fb + (size_t)c * S_);
            acc[c] += f.x * m0 + f.y * m1 + f.z * m2 + f.w * m3;
        }

        {
            unsigned part = nib << (((lane >> 1) & 7) * 4);
            part |= __shfl_xor_sync(0x55555555u, part, 2);
            part |= __shfl_xor_sync(0x55555555u, part, 4);
            part |= __shfl_xor_sync(0x55555555u, part, 8);
            if ((lane & 15) == 0) g_pos[v >> 5] = part;
        }
    }

#pragma unroll
    for (int c = 0; c < 16; c++) {
        acc[c] += __shfl_xor_sync(0xffffffffu, acc[c], 2);
        acc[c] += __shfl_xor_sync(0xffffffffu, acc[c], 4);
        acc[c] += __shfl_xor_sync(0xffffffffu, acc[c], 8);
        acc[c] += __shfl_xor_sync(0xffffffffu, acc[c], 16);
    }
    ce = warpRed(ce); sp = warpRed(sp); tp = warpRed(tp); cnt = warpRed(cnt);

    __shared__ float sh[8][36];
    const int w = threadIdx.x >> 5;
    if (lane < 2) {
#pragma unroll
        for (int c = 0; c < 16; c++) sh[w][half + c] = acc[c];
    }
    if (lane == 0) { sh[w][32] = ce; sh[w][33] = sp; sh[w][34] = tp; sh[w][35] = cnt; }
    __syncthreads();
    if (threadIdx.x < 36) {
        float t = 0.f;
#pragma unroll
        for (int u = 0; u < 8; u++) t += sh[u][threadIdx.x];
        atomicAdd(&g_accA[threadIdx.x], t);
    }
}

// ---------------- 2: normalize std ----------------
__global__ void kA2() {
    int c = threadIdx.x;                // 32 threads
    float cnt = g_accA[35];
    float std = (cnt > 0.f) ? g_accA[c] / fmaxf(cnt, 1.f) : 0.f;
    float sq = std * std;
#pragma unroll
    for (int o = 16; o; o >>= 1) sq += __shfl_xor_sync(0xffffffffu, sq, o);
    float nrm = sqrtf(sq);
    g_stdn[c] = std / fmaxf(nrm, 1e-12f);
}

// ---------------- 3: sim pass (feature read #2) + pos_loss + SMEM histogram ----------------
__global__ __launch_bounds__(256) void kB(const float* __restrict__ feat) {
    __shared__ float ssn[32];
    __shared__ int   shist[4096];
    if (threadIdx.x < 32) ssn[threadIdx.x] = g_stdn[threadIdx.x];
#pragma unroll
    for (int k = 0; k < 16; k++) shist[threadIdx.x + (k << 8)] = 0;
    __syncthreads();

    float psum = 0.f;
    const int stride = gridDim.x * blockDim.x;
    for (int i = blockIdx.x * blockDim.x + threadIdx.x; i < N_ / 4; i += stride) {
        const int q = (N_ / 4 - 1) - i;      // reversed quad index
        const int v = q << 2;
        const int b = v >> 20;
        const int s = v & (S_ - 1);
        const float* fb = feat + (size_t)b * 32 * S_ + s;

        float d0 = 0, d1 = 0, d2 = 0, d3 = 0, n0 = 0, n1 = 0, n2 = 0, n3 = 0;
#pragma unroll
        for (int c = 0; c < 32; c++) {
            const float4 f = *reinterpret_cast<const float4*>(fb + (size_t)c * S_);
            const float wc = ssn[c];
            d0 += f.x * wc; n0 += f.x * f.x;
            d1 += f.y * wc; n1 += f.y * f.y;
            d2 += f.z * wc; n2 += f.z * f.z;
            d3 += f.w * wc; n3 += f.w * f.w;
        }
        float sims[4];
        sims[0] = d0 / fmaxf(sqrtf(n0), 1e-12f);
        sims[1] = d1 / fmaxf(sqrtf(n1), 1e-12f);
        sims[2] = d2 / fmaxf(sqrtf(n2), 1e-12f);
        sims[3] = d3 / fmaxf(sqrtf(n3), 1e-12f);
        __stcs(reinterpret_cast<float4*>(g_sim + v),
               make_float4(sims[0], sims[1], sims[2], sims[3]));

        const unsigned pw = g_pos[v >> 5];
        const unsigned base = v & 31;
#pragma unroll
        for (int j = 0; j < 4; j++) {
            bool pos = (pw >> (base + j)) & 1u;
            if (pos) {
                psum += 1.f - sims[j];
            } else {
                int bin = (int)((sims[j] + 1.0f) * 2048.0f);
                bin = max(0, min(4095, bin));
                atomicAdd(&shist[bin], 1);
            }
        }
    }
    psum = warpRed(psum);
    __shared__ float shp[8];
    if ((threadIdx.x & 31) == 0) shp[threadIdx.x >> 5] = psum;
    __syncthreads();
    if (threadIdx.x == 0) {
        float t = 0.f;
#pragma unroll
        for (int u = 0; u < 8; u++) t += shp[u];
        atomicAdd(&g_possum, t);
    }
#pragma unroll
    for (int k = 0; k < 16; k++) {
        const int bin = threadIdx.x + (k << 8);
        const int val = shist[bin];
        if (val) atomicAdd(&g_hist[bin], val);
    }
}

// ---------------- bit-packed separable Chebyshev-10 dilation (pos mask only) ----------------
__global__ void kDilW() {               // g_pos -> g_t1
    int r = blockIdx.x * blockDim.x + threadIdx.x;
    if (r >= NROWS_) return;
    unsigned a0 = g_pos[r * 4 + 0], a1 = g_pos[r * 4 + 1], a2 = g_pos[r * 4 + 2], a3 = g_pos[r * 4 + 3];
    unsigned c0 = a0, c1 = a1, c2 = a2, c3 = a3;
#pragma unroll
    for (int s = 1; s <= 10; s++) {
        c0 |= (a0 << s) | __funnelshift_r(a0, a1, s);
        c1 |= __funnelshift_l(a0, a1, s) | __funnelshift_r(a1, a2, s);
        c2 |= __funnelshift_l(a1, a2, s) | __funnelshift_r(a2, a3, s);
        c3 |= __funnelshift_l(a2, a3, s) | (a3 >> s);
    }
    g_t1[r * 4 + 0] = c0; g_t1[r * 4 + 1] = c1; g_t1[r * 4 + 2] = c2; g_t1[r * 4 + 3] = c3;
}

__global__ void kDilH() {               // g_t1 -> g_t2
    int w = blockIdx.x * blockDim.x + threadIdx.x;
    if (w >= NW_) return;
    int k = w & 3, h = (w >> 2) & 127, base = (w >> 9) << 9;
    int h0 = max(h - 10, 0), h1 = min(h + 10, 127);
    unsigned acc = 0u;
    for (int hh = h0; hh <= h1; hh++) acc |= g_t1[base + (hh << 2) + k];
    g_t2[w] = acc;
}

__global__ void kDilD() {               // g_t2 -> g_dilP
    int w = blockIdx.x * blockDim.x + threadIdx.x;
    if (w >= NW_) return;
    int j = w & 511, d = (w >> 9) & 63, base = (w >> 15) << 15;
    int d0 = max(d - 10, 0), d1 = min(d + 10, 63);
    unsigned acc = 0u;
    for (int dd = d0; dd <= d1; dd++) acc |= g_t2[base + (dd << 9) + j];
    g_dilP[w] = acc;
}

// ---------------- top-k threshold bin via suffix scan (R11-proven) ----------------
__global__ void kT1() {
    __shared__ int shh[4096];
    __shared__ int ssum[1024];
    int t = threadIdx.x;
#pragma unroll
    for (int k = 0; k < 4; k++) shh[t * 4 + k] = g_hist[t * 4 + k];
    __syncthreads();
    ssum[t] = shh[t * 4] + shh[t * 4 + 1] + shh[t * 4 + 2] + shh[t * 4 + 3];
    __syncthreads();
    for (int off = 1; off < 1024; off <<= 1) {
        int add = (t + off < 1024) ? ssum[t + off] : 0;
        __syncthreads();
        ssum[t] += add;
        __syncthreads();
    }
    int run = (t < 1023) ? ssum[t + 1] : 0;   // suffix count strictly below this chunk's bins
    for (int k = 3; k >= 0; k--) {
        int nr = run + shh[t * 4 + k];
        if (run < TOPN && nr >= TOPN) g_bstar = t * 4 + k;  // exactly one thread writes
        run = nr;
    }
}

// ---------------- gather candidates >= threshold bin (R11-proven) ----------------
__global__ void kG() {
    const int stride = gridDim.x * blockDim.x;
    const int bstar = g_bstar;
    for (int i = blockIdx.x * blockDim.x + threadIdx.x; i < N_ / 4; i += stride) {
        const int v = i << 2;
        const unsigned pw = g_pos[v >> 5];
        const float4 sm = *reinterpret_cast<const float4*>(g_sim + v);
        float sims[4] = {sm.x, sm.y, sm.z, sm.w};
        const unsigned base = v & 31;
#pragma unroll
        for (int j = 0; j < 4; j++) {
            bool pos = (pw >> (base + j)) & 1u;
            if (!pos) {
                int bin = (int)((sims[j] + 1.0f) * 2048.0f);
                bin = max(0, min(4095, bin));
                if (bin >= bstar) {
                    int id = atomicAdd(&g_ccount, 1);
                    if (id < CAPC) { g_cval[id] = sims[j]; g_cidx[id] = v + j; }
                }
            }
        }
    }
}

// ---------------- top-250 selection + scatter dilation ----------------
// Grid = TOPN blocks. Selection loop identical in structure to R11's kS
// (value desc, index asc tie-break); block b owns the rank-b point and ORs
// its clamped radius-10 Chebyshev box into g_dilH. Union of clamped boxes
// == dense dilation of the top-k mask.
__global__ __launch_bounds__(256) void kS2() {
    __shared__ float sv[CAPC];
    __shared__ int   si[CAPC];
    __shared__ int   spt;
    int K = g_ccount; if (K > CAPC) K = CAPC;
    if (threadIdx.x == 0) spt = -1;
    for (int i = threadIdx.x; i < K; i += blockDim.x) { sv[i] = g_cval[i]; si[i] = g_cidx[i]; }
    __syncthreads();
    for (int i = threadIdx.x; i < K; i += blockDim.x) {
        float v = sv[i]; int id = si[i];
        int rank = 0;
        for (int j = 0; j < K; j++) {
            float vj = sv[j];
            rank += (vj > v) || (vj == v && si[j] < id);
        }
        if (rank == (int)blockIdx.x) spt = id;    // ranks unique -> single writer
    }
    __syncthreads();
    const int id = spt;
    if (id < 0) return;

    const int w0 = id & 127;
    const int h0 = (id >> 7) & 127;
    const int d0 = (id >> 14) & 63;
    const int wordbase_b = (id >> 20) << 15;       // batch * 32768 words

    // 128-bit W mask covering bits [max(w0-10,0), min(w0+10,127)]
    const int lo = max(w0 - 10, 0), hi = min(w0 + 10, 127);
    unsigned wm[4];
#pragma unroll
    for (int k = 0; k < 4; k++) {
        int a = max(lo - k * 32, 0), bb = min(hi + 1 - k * 32, 32);
        wm[k] = 0u;
        if (bb > a) {
            unsigned m = (bb - a == 32) ? 0xffffffffu : ((1u << (bb - a)) - 1u);
            wm[k] = m << a;
        }
    }

    // 21*21 = 441 (d,h) pairs, strided over 256 threads
    for (int t = threadIdx.x; t < 21 * 21; t += blockDim.x) {
        const int dd = d0 - 10 + t / 21;
        const int hh = h0 - 10 + t % 21;
        if (dd < 0 || dd > 63 || hh < 0 || hh > 127) continue;
        const int rowbase = wordbase_b + (dd << 9) + (hh << 2);
#pragma unroll
        for (int k = 0; k < 4; k++)
            if (wm[k]) atomicOr(&g_dilH[rowbase + k], wm[k]);
    }
}

// ---------------- mis + fin accumulation ----------------
__global__ __launch_bounds__(256) void kF() {
    float ms = 0.f, mc = 0.f, fs = 0.f, fc = 0.f;
    const int stride = gridDim.x * blockDim.x;
    for (int i = blockIdx.x * blockDim.x + threadIdx.x; i < N_ / 4; i += stride) {
        const int v = i << 2;
        const unsigned pw = g_pos[v >> 5], dp = g_dilP[v >> 5], dh = g_dilH[v >> 5];
        const float4 sm = *reinterpret_cast<const float4*>(g_sim + v);
        float sims[4] = {sm.x, sm.y, sm.z, sm.w};
        const unsigned base = v & 31;
#pragma unroll
        for (int j = 0; j < 4; j++) {
            unsigned bit = base + j;
            bool pos = (pw >> bit) & 1u;
            float r = fmaxf(sims[j], 0.f);
            if (((dp >> bit) & 1u) && !pos) { ms += r; mc += 1.f; }
            if (((dh >> bit) & 1u) && !pos) { fs += r; fc += 1.f; }
        }
    }
    ms = warpRed(ms); mc = warpRed(mc); fs = warpRed(fs); fc = warpRed(fc);
    __shared__ float sh4[8][4];
    if ((threadIdx.x & 31) == 0) {
        int w = threadIdx.x >> 5;
        sh4[w][0] = ms; sh4[w][1] = mc; sh4[w][2] = fs; sh4[w][3] = fc;
    }
    __syncthreads();
    if (threadIdx.x < 4) {
        float t = 0.f;
#pragma unroll
        for (int u = 0; u < 8; u++) t += sh4[u][threadIdx.x];
        if      (threadIdx.x == 0) atomicAdd(&g_msum, t);
        else if (threadIdx.x == 1) atomicAdd(&g_mcnt, t);
        else if (threadIdx.x == 2) atomicAdd(&g_fsum, t);
        else                       atomicAdd(&g_fcnt, t);
    }
}

// ---------------- final combine ----------------
__global__ void kZ(float* __restrict__ out) {
    const float Nf = (float)N_;
    float ce  = g_accA[32] / Nf;
    float sp  = g_accA[33], tp = g_accA[34], cnt = g_accA[35];
    float dc  = (2.f * tp + 1e-5f) / (sp + cnt + 1e-5f + 1e-8f);
    float dice = -dc;
    float pl = (cnt    > 0.f) ? g_possum / fmaxf(cnt,    1.f) : 0.f;
    float ml = (g_mcnt > 0.f) ? g_msum   / fmaxf(g_mcnt, 1.f) : 0.f;
    float nl = (g_fcnt > 0.f) ? g_fsum   / fmaxf(g_fcnt, 1.f) : 0.f;
    out[0] = ce + dice + 5.f * (pl + ml + nl);
}

// ---------------- launch ----------------
extern "C" void kernel_launch(void* const* d_in, const int* in_sizes, int n_in,
                              void* d_out, int out_size) {
    const float* feat = (const float*)d_in[0];
    const float* net  = (const float*)d_in[1];
    const int*   tgt  = (const int*)d_in[2];
    float* out = (float*)d_out;

    kInit<<<256, 256>>>();
    kA<<<2048, 256>>>(feat, net, tgt);
    kA2<<<1, 32>>>();
    kB<<<1024, 256>>>(feat);

    // dilate pos mask (dense, separable)
    kDilW<<<64, 256>>>();
    kDilH<<<256, 256>>>();
    kDilD<<<256, 256>>>();

    // top-250 of neg sims: threshold scan, gather, select + scatter-dilate
    kT1<<<1, 1024>>>();
    kG<<<256, 256>>>();
    kS2<<<TOPN, 256>>>();

    kF<<<512, 256>>>();
    kZ<<<1, 1>>>(out);
}